// round 7
// baseline (speedup 1.0000x reference)
#include <cuda_runtime.h>
#include <math.h>
#include <stdint.h>

#define B_ 32
#define S_ 1024
#define D_ 768
#define L_ 12
#define MTOT (B_*S_)

// ===================== scratch (__device__ globals; no allocs) =====================
__device__ __align__(16) float  g_h  [(size_t)MTOT*D_];
__device__ __align__(16) float  g_Qf [(size_t)MTOT*D_];
__device__ __align__(16) float  g_Kf [(size_t)MTOT*D_];
__device__ __align__(16) float  g_Vf [(size_t)MTOT*D_];
__device__ __align__(16) float  g_P  [(size_t)B_*S_*S_];
__device__ __align__(16) int8_t g_hq1[(size_t)MTOT*D_];
__device__ __align__(16) int8_t g_hq2[(size_t)MTOT*D_];
__device__ __align__(16) int8_t g_Qq1[(size_t)MTOT*D_];
__device__ __align__(16) int8_t g_Qq2[(size_t)MTOT*D_];
__device__ __align__(16) int8_t g_Kq1[(size_t)MTOT*D_];
__device__ __align__(16) int8_t g_Kq2[(size_t)MTOT*D_];
__device__ __align__(16) int8_t g_Vt1[(size_t)B_*D_*S_];
__device__ __align__(16) int8_t g_Vt2[(size_t)B_*D_*S_];
__device__ __align__(16) int8_t g_Pq1[(size_t)B_*S_*S_];
__device__ __align__(16) int8_t g_Pq2[(size_t)B_*S_*S_];
__device__ __align__(16) int8_t g_W1 [(size_t)3*L_*D_*D_];
__device__ __align__(16) int8_t g_W2 [(size_t)3*L_*D_*D_];
__device__ float g_hsc[MTOT];
__device__ float g_qsc[MTOT];
__device__ float g_ksc[MTOT];
__device__ float g_psc[MTOT];
__device__ float g_vsc[B_*D_];
__device__ float g_wsc[3*L_*D_];

// ===================== PTX helpers =====================
__device__ __forceinline__ uint32_t smem_u32(const void* p) {
    uint32_t a;
    asm("{ .reg .u64 t; cvta.to.shared.u64 t, %1; cvt.u32.u64 %0, t; }" : "=r"(a) : "l"(p));
    return a;
}
__device__ __forceinline__ void cpa16(uint32_t s, const void* g) {
    asm volatile("cp.async.cg.shared.global [%0], [%1], 16;" :: "r"(s), "l"(g));
}
#define CP_COMMIT() asm volatile("cp.async.commit_group;" ::: "memory")
#define CP_WAIT1()  asm volatile("cp.async.wait_group 1;" ::: "memory")

__device__ __forceinline__ void ldm_x4(uint32_t& r0, uint32_t& r1, uint32_t& r2, uint32_t& r3,
                                       uint32_t a) {
    asm volatile("ldmatrix.sync.aligned.m8n8.x4.shared.b16 {%0,%1,%2,%3}, [%4];"
                 : "=r"(r0), "=r"(r1), "=r"(r2), "=r"(r3) : "r"(a));
}
__device__ __forceinline__ void mma_s8(int* c, const uint32_t* a, const uint32_t* b) {
    asm volatile("mma.sync.aligned.m16n8k32.row.col.s32.s8.s8.s32 "
                 "{%0,%1,%2,%3}, {%4,%5,%6,%7}, {%8,%9}, {%0,%1,%2,%3};"
                 : "+r"(c[0]), "+r"(c[1]), "+r"(c[2]), "+r"(c[3])
                 : "r"(a[0]), "r"(a[1]), "r"(a[2]), "r"(a[3]), "r"(b[0]), "r"(b[1]));
}

// 2-digit int8 quantize: x ~= s*(256*q1 + q2); inv = 1/s
__device__ __forceinline__ void quant2(float x, float inv, int8_t& o1, int8_t& o2) {
    const float xs = x * inv;
    float a = rintf(xs * 0.00390625f);
    float b = rintf(xs - 256.f * a);
    b = fminf(b, 127.f);
    o1 = (int8_t)(int)a;
    o2 = (int8_t)(int)b;
}

// ===================== int8 GEMM: C = alpha*sA[m]*sB[n]*(65536*c11+256*cx) (+bias)(*csc)
#define BM 128
#define BN 64
#define BKE 64                        // int8 k per stage
#define ROWB 80                       // 64B + 16B pad, conflict-free for ldmatrix
#define TILE_A (BM*ROWB)              // 10240
#define TILE_B (BN*ROWB)              // 5120
#define STAGEB (2*TILE_A + 2*TILE_B)  // 30720
#define GEMM_SMEM (2*STAGEB)          // 61440

__global__ __launch_bounds__(256, 1)
void gemm_i8(const int8_t* __restrict__ A1, const int8_t* __restrict__ A2,
             const float* __restrict__ sA,
             const int8_t* __restrict__ B1, const int8_t* __restrict__ B2,
             const float* __restrict__ sB,
             float* __restrict__ C,
             const float* __restrict__ bias, const float* __restrict__ csc,
             float alpha, int K, int lda, int ldb, int ldc,
             long strA, long strB, long strC, long strSA, long strSB)
{
    extern __shared__ char smem[];
    const uint32_t sbase = smem_u32(smem);
    const int tid = threadIdx.x, lane = tid & 31, wid = tid >> 5;
    const int wm = wid & 3, wn = wid >> 2;      // 4(M) x 2(N) warps; warp tile 32x32
    const int z = blockIdx.z;
    A1 += z * strA;  A2 += z * strA;
    B1 += z * strB;  B2 += z * strB;
    sA += z * strSA; sB += z * strSB;
    C  += z * strC;

    const long tileM = blockIdx.y * (long)BM;
    const long tileN = blockIdx.x * (long)BN;
    const int8_t* gA1 = A1 + tileM * lda;
    const int8_t* gA2 = A2 + tileM * lda;
    const int8_t* gB1 = B1 + tileN * ldb;
    const int8_t* gB2 = B2 + tileN * ldb;

    auto load_stage = [&](int stage, int k0) {
        const uint32_t sb = sbase + stage * STAGEB;
        #pragma unroll
        for (int it = 0; it < 2; it++) {
            const int idx = tid + it * 256;     // 512 chunks: 128 rows x 4 x 16B
            const int r = idx >> 2, c = idx & 3;
            const long go = (long)r * lda + k0 + c * 16;
            const uint32_t so = r * ROWB + c * 16;
            cpa16(sb + so, gA1 + go);
            cpa16(sb + TILE_A + so, gA2 + go);
        }
        {
            const int r = tid >> 2, c = tid & 3; // 256 chunks: 64 rows x 4 x 16B
            const long go = (long)r * ldb + k0 + c * 16;
            const uint32_t so = r * ROWB + c * 16;
            cpa16(sb + 2*TILE_A + so, gB1 + go);
            cpa16(sb + 2*TILE_A + TILE_B + so, gB2 + go);
        }
        CP_COMMIT();
    };

    int c11[2][4][4], cx[2][4][4];
    #pragma unroll
    for (int i = 0; i < 2; i++)
        #pragma unroll
        for (int j = 0; j < 4; j++)
            #pragma unroll
            for (int q = 0; q < 4; q++) { c11[i][j][q] = 0; cx[i][j][q] = 0; }

    const int nk = K / BKE;
    load_stage(0, 0);
    load_stage(1, BKE);

    const int a_row = wm * 32 + (lane & 15);
    const int b_row = wn * 32 + (lane & 7) + ((lane >> 3) & 1) * 8;
    const int colb  = (lane >> 4) * 16;

    for (int i = 0; i < nk; i++) {
        CP_WAIT1();
        __syncthreads();
        const uint32_t sb = sbase + (i & 1) * STAGEB;

        #pragma unroll
        for (int ks = 0; ks < 2; ks++) {
            uint32_t a1f[2][4], a2f[2][4], b1f[4][2], b2f[4][2];
            #pragma unroll
            for (int ma = 0; ma < 2; ma++) {
                const uint32_t ad = sb + (a_row + ma * 16) * ROWB + ks * 32 + colb;
                ldm_x4(a1f[ma][0], a1f[ma][1], a1f[ma][2], a1f[ma][3], ad);
                ldm_x4(a2f[ma][0], a2f[ma][1], a2f[ma][2], a2f[ma][3], ad + TILE_A);
            }
            #pragma unroll
            for (int nb = 0; nb < 2; nb++) {
                const uint32_t bd = sb + 2*TILE_A + (b_row + nb * 16) * ROWB + ks * 32 + colb;
                uint32_t t0, t1, t2, t3;
                ldm_x4(t0, t1, t2, t3, bd);
                b1f[2*nb][0] = t0; b1f[2*nb][1] = t2; b1f[2*nb+1][0] = t1; b1f[2*nb+1][1] = t3;
                ldm_x4(t0, t1, t2, t3, bd + TILE_B);
                b2f[2*nb][0] = t0; b2f[2*nb][1] = t2; b2f[2*nb+1][0] = t1; b2f[2*nb+1][1] = t3;
            }
            #pragma unroll
            for (int ma = 0; ma < 2; ma++)
                #pragma unroll
                for (int na = 0; na < 4; na++) mma_s8(c11[ma][na], a1f[ma], b1f[na]);
            #pragma unroll
            for (int ma = 0; ma < 2; ma++)
                #pragma unroll
                for (int na = 0; na < 4; na++) mma_s8(cx[ma][na], a1f[ma], b2f[na]);
            #pragma unroll
            for (int ma = 0; ma < 2; ma++)
                #pragma unroll
                for (int na = 0; na < 4; na++) mma_s8(cx[ma][na], a2f[ma], b1f[na]);
        }

        __syncthreads();
        if (i + 2 < nk) load_stage(i & 1, (i + 2) * BKE);
        else CP_COMMIT();
    }

    // epilogue
    const int gq = lane >> 2, rq = lane & 3;
    #pragma unroll
    for (int ma = 0; ma < 2; ma++) {
        #pragma unroll
        for (int half = 0; half < 2; half++) {
            const long row = tileM + wm * 32 + ma * 16 + gq + half * 8;
            const float sa = sA[row] * alpha;
            #pragma unroll
            for (int na = 0; na < 4; na++) {
                const long col = tileN + wn * 32 + na * 8 + rq * 2;
                const int ix = half * 2;
                float v0 = sa * sB[col]   * (65536.f * (float)c11[ma][na][ix]
                                            + 256.f * (float)cx[ma][na][ix]);
                float v1 = sa * sB[col+1] * (65536.f * (float)c11[ma][na][ix+1]
                                            + 256.f * (float)cx[ma][na][ix+1]);
                if (bias) { v0 += bias[col]; v1 += bias[col+1]; }
                if (csc)  { v0 *= csc[col];  v1 *= csc[col+1]; }
                float2 f2; f2.x = v0; f2.y = v1;
                *(float2*)(C + row * ldc + col) = f2;
            }
        }
    }
}

// ===================== per-row quantize, row length 768 =====================
__global__ __launch_bounds__(256)
void quant_rows768(const float* __restrict__ X, int8_t* __restrict__ Q1,
                   int8_t* __restrict__ Q2, float* __restrict__ sc)
{
    const long row = blockIdx.x;
    const float* x = X + row * D_;
    const int tid = threadIdx.x;
    __shared__ float red[8];

    const float v0 = x[tid], v1 = x[tid + 256], v2 = x[tid + 512];
    float m = fmaxf(fabsf(v0), fmaxf(fabsf(v1), fabsf(v2)));
    #pragma unroll
    for (int o = 16; o; o >>= 1) m = fmaxf(m, __shfl_xor_sync(0xFFFFFFFFu, m, o));
    if ((tid & 31) == 0) red[tid >> 5] = m;
    __syncthreads();
    if (tid < 8) {
        float t = red[tid];
        #pragma unroll
        for (int o = 4; o; o >>= 1) t = fmaxf(t, __shfl_xor_sync(0xFFu, t, o));
        if (tid == 0) red[0] = t;
    }
    __syncthreads();
    const float s = fmaxf(red[0], 1e-20f) / 32512.f;
    const float inv = 1.f / s;

    int8_t a, b;
    quant2(v0, inv, a, b); Q1[row*D_ + tid]       = a; Q2[row*D_ + tid]       = b;
    quant2(v1, inv, a, b); Q1[row*D_ + tid + 256] = a; Q2[row*D_ + tid + 256] = b;
    quant2(v2, inv, a, b); Q1[row*D_ + tid + 512] = a; Q2[row*D_ + tid + 512] = b;
    if (tid == 0) sc[row] = s;
}

// ===================== column abs-max -> scale =====================
__global__ void colmax_abs(const float* __restrict__ X, float* __restrict__ sc,
                           int R, int C, long sX, long sSc)
{
    const int c = blockIdx.x * 128 + threadIdx.x;
    const float* x = X + blockIdx.y * sX + c;
    float m = 1e-20f;
    for (int r = 0; r < R; r += 4) {
        m = fmaxf(m, fabsf(x[(long)r * C]));
        m = fmaxf(m, fabsf(x[(long)(r+1) * C]));
        m = fmaxf(m, fabsf(x[(long)(r+2) * C]));
        m = fmaxf(m, fabsf(x[(long)(r+3) * C]));
    }
    sc[blockIdx.y * sSc + c] = m / 32512.f;
}

// ===================== transpose + quantize: X(R,C) -> T(C,R) int8x2 ==============
__global__ void transpose_quant(const float* __restrict__ X,
                                int8_t* __restrict__ T1, int8_t* __restrict__ T2,
                                const float* __restrict__ sc,
                                int R, int C, long sX, long sT, long sSc)
{
    __shared__ float t[32][33];
    const int z = blockIdx.z;
    X += z * sX; T1 += z * sT; T2 += z * sT; sc += z * sSc;
    const int c0 = blockIdx.x * 32, r0 = blockIdx.y * 32;
    const int tx = threadIdx.x, ty = threadIdx.y;
    #pragma unroll
    for (int k = 0; k < 4; k++)
        t[ty + 8*k][tx] = X[(long)(r0 + ty + 8*k) * C + c0 + tx];
    __syncthreads();
    #pragma unroll
    for (int k = 0; k < 4; k++) {
        const int orow = c0 + ty + 8*k;
        const float inv = 1.f / sc[orow];
        int8_t a, b;
        quant2(t[tx][ty + 8*k], inv, a, b);
        const long o = (long)orow * R + r0 + tx;
        T1[o] = a; T2[o] = b;
    }
}

// ===================== row softmax -> int8x2 (exact digits from e_i) ==============
__global__ __launch_bounds__(256)
void softmax_quant(const float* __restrict__ P, int8_t* __restrict__ Q1,
                   int8_t* __restrict__ Q2, float* __restrict__ psc)
{
    const long row = blockIdx.x;
    const int tid = threadIdx.x;
    __shared__ float red[8];

    const float4 f = *(const float4*)(P + row * S_ + tid * 4);
    float v[4] = {f.x, f.y, f.z, f.w};

    float m = fmaxf(fmaxf(v[0], v[1]), fmaxf(v[2], v[3]));
    #pragma unroll
    for (int o = 16; o; o >>= 1) m = fmaxf(m, __shfl_xor_sync(0xFFFFFFFFu, m, o));
    if ((tid & 31) == 0) red[tid >> 5] = m;
    __syncthreads();
    if (tid < 8) {
        float t = red[tid];
        #pragma unroll
        for (int o = 4; o; o >>= 1) t = fmaxf(t, __shfl_xor_sync(0xFFu, t, o));
        if (tid == 0) red[0] = t;
    }
    __syncthreads();
    m = red[0];
    __syncthreads();

    float s = 0.f;
    #pragma unroll
    for (int k = 0; k < 4; k++) { v[k] = __expf(v[k] - m); s += v[k]; }
    #pragma unroll
    for (int o = 16; o; o >>= 1) s += __shfl_xor_sync(0xFFFFFFFFu, s, o);
    if ((tid & 31) == 0) red[tid >> 5] = s;
    __syncthreads();
    if (tid < 8) {
        float t = red[tid];
        #pragma unroll
        for (int o = 4; o; o >>= 1) t += __shfl_xor_sync(0xFFu, t, o);
        if (tid == 0) red[0] = t;
    }
    __syncthreads();
    const float Z = red[0];

    char q1[4], q2[4];
    #pragma unroll
    for (int k = 0; k < 4; k++) {
        const float xs = 32512.f * v[k];
        float a = rintf(xs * 0.00390625f);
        float b = fminf(rintf(xs - 256.f * a), 127.f);
        q1[k] = (char)(int)a;
        q2[k] = (char)(int)b;
    }
    *(char4*)(Q1 + row * S_ + tid * 4) = *(const char4*)q1;
    *(char4*)(Q2 + row * S_ + tid * 4) = *(const char4*)q2;
    if (tid == 0) psc[row] = 1.f / (32512.f * Z);
}

// ===================== head =====================
__global__ __launch_bounds__(256)
void head_kernel(const float* __restrict__ h, const float* __restrict__ Wh,
                 const float* __restrict__ bh, float* __restrict__ out)
{
    const int b = blockIdx.x;
    const float* p = h + (long)b * S_ * D_;
    const int tid = threadIdx.x;
    __shared__ float red[8];

    float s = 0.f;
    for (int d = tid; d < D_; d += 256) s += p[d] * Wh[d];
    #pragma unroll
    for (int o = 16; o; o >>= 1) s += __shfl_xor_sync(0xFFFFFFFFu, s, o);
    if ((tid & 31) == 0) red[tid >> 5] = s;
    __syncthreads();
    if (tid == 0) {
        float t = 0.f;
        #pragma unroll
        for (int w = 0; w < 8; w++) t += red[w];
        out[b] = t + bh[0];
    }
}

// ===================== driver =====================
extern "C" void kernel_launch(void* const* d_in, const int* in_sizes, int n_in,
                              void* d_out, int out_size)
{
    const float* hs    = (const float*)d_in[0];
    const float* Wq    = (const float*)d_in[1];
    const float* bq    = (const float*)d_in[2];
    const float* Wk    = (const float*)d_in[3];
    const float* bk    = (const float*)d_in[4];
    const float* Wv    = (const float*)d_in[5];
    const float* bv    = (const float*)d_in[6];
    const float* lk    = (const float*)d_in[7];
    const float* lv    = (const float*)d_in[8];
    const float* Whead = (const float*)d_in[9];
    const float* bhead = (const float*)d_in[10];
    float* out = (float*)d_out;

    float *h, *Qf, *Kf, *Vf, *P, *hsc, *qsc, *ksc, *psc, *vsc, *wsc;
    int8_t *hq1, *hq2, *Qq1, *Qq2, *Kq1, *Kq2, *Vt1, *Vt2, *Pq1, *Pq2, *W1, *W2;
    cudaGetSymbolAddress((void**)&h,   g_h);
    cudaGetSymbolAddress((void**)&Qf,  g_Qf);  cudaGetSymbolAddress((void**)&Kf,  g_Kf);
    cudaGetSymbolAddress((void**)&Vf,  g_Vf);  cudaGetSymbolAddress((void**)&P,   g_P);
    cudaGetSymbolAddress((void**)&hq1, g_hq1); cudaGetSymbolAddress((void**)&hq2, g_hq2);
    cudaGetSymbolAddress((void**)&Qq1, g_Qq1); cudaGetSymbolAddress((void**)&Qq2, g_Qq2);
    cudaGetSymbolAddress((void**)&Kq1, g_Kq1); cudaGetSymbolAddress((void**)&Kq2, g_Kq2);
    cudaGetSymbolAddress((void**)&Vt1, g_Vt1); cudaGetSymbolAddress((void**)&Vt2, g_Vt2);
    cudaGetSymbolAddress((void**)&Pq1, g_Pq1); cudaGetSymbolAddress((void**)&Pq2, g_Pq2);
    cudaGetSymbolAddress((void**)&W1,  g_W1);  cudaGetSymbolAddress((void**)&W2,  g_W2);
    cudaGetSymbolAddress((void**)&hsc, g_hsc); cudaGetSymbolAddress((void**)&qsc, g_qsc);
    cudaGetSymbolAddress((void**)&ksc, g_ksc); cudaGetSymbolAddress((void**)&psc, g_psc);
    cudaGetSymbolAddress((void**)&vsc, g_vsc); cudaGetSymbolAddress((void**)&wsc, g_wsc);

    cudaFuncSetAttribute(gemm_i8, cudaFuncAttributeMaxDynamicSharedMemorySize, GEMM_SMEM);

    const float attn_alpha = 1.0f / sqrtf((float)D_);
    const long SD = (long)S_ * D_;
    const long SS = (long)S_ * S_;
    const long DD = (long)D_ * D_;
    const long LD = (long)L_ * D_;

    // ---- prep: quantize hidden states; transpose+quantize all weights ----
    quant_rows768<<<MTOT, 256>>>(hs, hq1, hq2, hsc);
    {
        const dim3 cb(128);
        colmax_abs<<<dim3(D_/128, L_), cb>>>(Wq, wsc + 0*LD, D_, D_, DD, D_);
        colmax_abs<<<dim3(D_/128, L_), cb>>>(Wk, wsc + 1*LD, D_, D_, DD, D_);
        colmax_abs<<<dim3(D_/128, L_), cb>>>(Wv, wsc + 2*LD, D_, D_, DD, D_);
        const dim3 tb(32, 8);
        const dim3 tg(D_/32, D_/32, L_);
        transpose_quant<<<tg, tb>>>(Wq, W1 + 0*L_*DD, W2 + 0*L_*DD, wsc + 0*LD, D_, D_, DD, DD, D_);
        transpose_quant<<<tg, tb>>>(Wk, W1 + 1*L_*DD, W2 + 1*L_*DD, wsc + 1*LD, D_, D_, DD, DD, D_);
        transpose_quant<<<tg, tb>>>(Wv, W1 + 2*L_*DD, W2 + 2*L_*DD, wsc + 2*LD, D_, D_, DD, DD, D_);
    }

    const dim3 blk(256);
    const dim3 grid_proj(D_/BN, MTOT/BM, 1);    // (12, 256, 1)
    const dim3 grid_qk(S_/BN, S_/BM, B_);       // (16, 8, 32)
    const dim3 grid_pv(D_/BN, S_/BM, B_);       // (12, 8, 32)

    for (int l = 0; l < L_; l++) {
        const long wo = (long)l * DD;
        const float* bq_i = bq + (long)l * D_;
        const float* bk_i = bk + (long)l * D_;
        const float* bv_i = bv + (long)l * D_;
        const float* lk_i = lk + (long)l * D_;
        const float* lv_i = lv + (long)l * D_;

        // Q = h @ Wq + bq
        gemm_i8<<<grid_proj, blk, GEMM_SMEM>>>(
            hq1, hq2, hsc, W1 + 0*L_*DD + wo, W2 + 0*L_*DD + wo, wsc + 0*LD + (long)l*D_,
            Qf, bq_i, nullptr, 1.0f, D_, D_, D_, D_, 0, 0, 0, 0, 0);
        // K = (h @ Wk + bk) * lk
        gemm_i8<<<grid_proj, blk, GEMM_SMEM>>>(
            hq1, hq2, hsc, W1 + 1*L_*DD + wo, W2 + 1*L_*DD + wo, wsc + 1*LD + (long)l*D_,
            Kf, bk_i, lk_i, 1.0f, D_, D_, D_, D_, 0, 0, 0, 0, 0);
        // V = (h @ Wv + bv) * lv
        gemm_i8<<<grid_proj, blk, GEMM_SMEM>>>(
            hq1, hq2, hsc, W1 + 2*L_*DD + wo, W2 + 2*L_*DD + wo, wsc + 2*LD + (long)l*D_,
            Vf, bv_i, lv_i, 1.0f, D_, D_, D_, D_, 0, 0, 0, 0, 0);

        // quantize Q, K per row
        quant_rows768<<<MTOT, 256>>>(Qf, Qq1, Qq2, qsc);
        quant_rows768<<<MTOT, 256>>>(Kf, Kq1, Kq2, ksc);
        // V: per (b,d) scale + transpose-quantize to (B, D, S)
        colmax_abs<<<dim3(D_/128, B_), dim3(128)>>>(Vf, vsc, S_, D_, SD, D_);
        transpose_quant<<<dim3(D_/32, S_/32, B_), dim3(32, 8)>>>(
            Vf, Vt1, Vt2, vsc, S_, D_, SD, SD, D_);

        // P = alpha * Q @ K^T
        gemm_i8<<<grid_qk, blk, GEMM_SMEM>>>(
            Qq1, Qq2, qsc, Kq1, Kq2, ksc, P,
            nullptr, nullptr, attn_alpha, D_, D_, D_, S_, SD, SD, SS, S_, S_);
        // softmax + quantize P
        softmax_quant<<<B_ * S_, blk>>>(P, Pq1, Pq2, psc);
        // h = P @ V  (= Pq @ Vt^T)
        gemm_i8<<<grid_pv, blk, GEMM_SMEM>>>(
            Pq1, Pq2, psc, Vt1, Vt2, vsc, h,
            nullptr, nullptr, 1.0f, S_, S_, S_, D_, SS, SD, SD, S_, D_);
        // quantize h for next layer
        quant_rows768<<<MTOT, 256>>>(h, hq1, hq2, hsc);
    }

    head_kernel<<<B_, blk>>>(h, Whead, bhead, out);
}

// round 10
// speedup vs baseline: 2.2774x; 2.2774x over previous
#include <cuda_runtime.h>
#include <cuda_bf16.h>
#include <math.h>
#include <stdint.h>

#define B_ 32
#define S_ 1024
#define D_ 768
#define L_ 12
#define SDW ((size_t)B_*S_*D_)

// ===================== scratch (__device__ globals; no allocs) =====================
__device__ __align__(16) __nv_bfloat16 g_hh  [(size_t)B_*S_*D_];
__device__ __align__(16) __nv_bfloat16 g_hl  [(size_t)B_*S_*D_];
__device__ __align__(16) __nv_bfloat16 g_QKVh[(size_t)3*B_*S_*D_];   // slabs: Q,K,V
__device__ __align__(16) __nv_bfloat16 g_QKVl[(size_t)3*B_*S_*D_];
__device__ __align__(16) __nv_bfloat16 g_Vth [(size_t)B_*S_*D_];     // (B, D, S)
__device__ __align__(16) __nv_bfloat16 g_Vtl [(size_t)B_*S_*D_];
__device__ __align__(16) float         g_P   [(size_t)B_*S_*S_];
__device__ __align__(16) __nv_bfloat16 g_Ph  [(size_t)B_*S_*S_];
__device__ __align__(16) __nv_bfloat16 g_Pl  [(size_t)B_*S_*S_];
__device__ __align__(16) __nv_bfloat16 g_Wth [(size_t)3*L_*D_*D_];   // slabs: Wq,Wk,Wv (N,K)
__device__ __align__(16) __nv_bfloat16 g_Wtl [(size_t)3*L_*D_*D_];
__device__ float g_biasP[(size_t)3*L_*D_];   // packed bq,bk,bv
__device__ float g_cscP [(size_t)3*L_*D_];   // packed 1, lk, lv

// ===================== PTX helpers (generic sm_80+ features only) =====================
__device__ __forceinline__ uint32_t smem_u32(const void* p) {
    uint32_t a;
    asm("{ .reg .u64 t; cvta.to.shared.u64 t, %1; cvt.u32.u64 %0, t; }" : "=r"(a) : "l"(p));
    return a;
}
__device__ __forceinline__ void cpa16(uint32_t s, const void* g) {
    asm volatile("cp.async.cg.shared.global [%0], [%1], 16;" :: "r"(s), "l"(g));
}
#define CP_COMMIT() asm volatile("cp.async.commit_group;" ::: "memory")
#define CP_WAIT1()  asm volatile("cp.async.wait_group 1;" ::: "memory")

__device__ __forceinline__ void ldm_x4(uint32_t& r0, uint32_t& r1, uint32_t& r2, uint32_t& r3,
                                       uint32_t a) {
    asm volatile("ldmatrix.sync.aligned.m8n8.x4.shared.b16 {%0,%1,%2,%3}, [%4];"
                 : "=r"(r0), "=r"(r1), "=r"(r2), "=r"(r3) : "r"(a));
}
__device__ __forceinline__ void mma_bf16(float* c, const uint32_t* a, const uint32_t* b) {
    asm volatile("mma.sync.aligned.m16n8k16.row.col.f32.bf16.bf16.f32 "
                 "{%0,%1,%2,%3}, {%4,%5,%6,%7}, {%8,%9}, {%0,%1,%2,%3};"
                 : "+f"(c[0]), "+f"(c[1]), "+f"(c[2]), "+f"(c[3])
                 : "r"(a[0]), "r"(a[1]), "r"(a[2]), "r"(a[3]), "r"(b[0]), "r"(b[1]));
}

// ===================== GEMM: C[M,N] = alpha * (A @ Bt^T) (+bias[z])(*csc[z]) =========
// A: [M,K] row-major split (Ah,Al).  Bt: [N,K] row-major split (Bh,Bl).
// bf16x3: acc += AhBh + AhBl + AlBh  (fp32 accum).
// OUT=0: fp32 C.  OUT=1: bf16 hi/lo split (Ch, Cl).
#define BM 128
#define BN 128
#define BKE 32                       // K elems per stage
#define ROWB 80                      // padded row bytes (32 bf16 = 64B + 16B pad)
#define TILEB (128 * ROWB)           // 10240 B per tile
#define STAGEB (4 * TILEB)           // Ah, Al, Bh, Bl = 40960 B
#define GEMM_SMEM (2 * STAGEB)       // 81920 B

template<int OUT>
__global__ __launch_bounds__(256, 2)
void gemm_mma(const __nv_bfloat16* __restrict__ Ah, const __nv_bfloat16* __restrict__ Al,
              const __nv_bfloat16* __restrict__ Bh, const __nv_bfloat16* __restrict__ Bl,
              float* __restrict__ Cf,
              __nv_bfloat16* __restrict__ Ch, __nv_bfloat16* __restrict__ Cl,
              const float* __restrict__ bias, const float* __restrict__ csc,
              float alpha, int K, int lda, int ldb, int ldc,
              long sA, long sB, long sC, long sBias, long sCsc)
{
    extern __shared__ char smem[];
    const uint32_t sbase = smem_u32(smem);
    const int tid = threadIdx.x;
    const int lane = tid & 31, wid = tid >> 5;
    const int wm = wid & 3, wn = wid >> 2;          // 4 (M) x 2 (N) warps
    const int z = blockIdx.z;
    Ah += z * sA;  Al += z * sA;
    Bh += z * sB;  Bl += z * sB;

    const long tileM = blockIdx.y * (long)BM;
    const long tileN = blockIdx.x * (long)BN;

    const __nv_bfloat16* gAh = Ah + tileM * lda;
    const __nv_bfloat16* gAl = Al + tileM * lda;
    const __nv_bfloat16* gBh = Bh + tileN * ldb;
    const __nv_bfloat16* gBl = Bl + tileN * ldb;

    // per-thread load slots: 128 rows x 4 chunks (16B) = 512 slots, 2 per thread
    const int r0q = tid >> 2, c0q = tid & 3;

    auto load_stage = [&](int stage, int k0) {
        const uint32_t sb = sbase + stage * STAGEB;
        #pragma unroll
        for (int it = 0; it < 2; it++) {
            const int r = r0q + it * 64;
            const long go = (long)r * lda + k0 + c0q * 8;
            const long gb = (long)r * ldb + k0 + c0q * 8;
            const uint32_t so = r * ROWB + c0q * 16;
            cpa16(sb + 0 * TILEB + so, gAh + go);
            cpa16(sb + 1 * TILEB + so, gAl + go);
            cpa16(sb + 2 * TILEB + so, gBh + gb);
            cpa16(sb + 3 * TILEB + so, gBl + gb);
        }
        CP_COMMIT();
    };

    float acc[2][8][4];
    #pragma unroll
    for (int i = 0; i < 2; i++)
        #pragma unroll
        for (int j = 0; j < 8; j++)
            #pragma unroll
            for (int q = 0; q < 4; q++) acc[i][j][q] = 0.f;

    const int nk = K / BKE;
    load_stage(0, 0);
    load_stage(1, BKE);

    // ldmatrix per-thread address components
    const int a_row  = wm * 32 + (lane & 15);                          // + ma*16
    const int b_row  = wn * 64 + (lane & 7) + ((lane >> 3) & 1) * 8;   // + nb*16
    const int colb   = (lane >> 4) * 16;                               // + ks*32

    for (int i = 0; i < nk; i++) {
        CP_WAIT1();
        __syncthreads();
        const uint32_t sb = sbase + (i & 1) * STAGEB;

        #pragma unroll
        for (int ks = 0; ks < 2; ks++) {
            uint32_t ah[2][4], al[2][4], bh[8][2], bl[8][2];
            #pragma unroll
            for (int ma = 0; ma < 2; ma++) {
                const uint32_t ad = sb + (a_row + ma * 16) * ROWB + ks * 32 + colb;
                ldm_x4(ah[ma][0], ah[ma][1], ah[ma][2], ah[ma][3], ad);
                ldm_x4(al[ma][0], al[ma][1], al[ma][2], al[ma][3], ad + TILEB);
            }
            #pragma unroll
            for (int nb = 0; nb < 4; nb++) {
                const uint32_t bd = sb + 2 * TILEB + (b_row + nb * 16) * ROWB + ks * 32 + colb;
                uint32_t t0, t1, t2, t3;
                ldm_x4(t0, t1, t2, t3, bd);
                bh[2*nb][0] = t0; bh[2*nb][1] = t2; bh[2*nb+1][0] = t1; bh[2*nb+1][1] = t3;
                ldm_x4(t0, t1, t2, t3, bd + TILEB);
                bl[2*nb][0] = t0; bl[2*nb][1] = t2; bl[2*nb+1][0] = t1; bl[2*nb+1][1] = t3;
            }
            // product-major ordering: 16 independent accs between dependent MMAs
            #pragma unroll
            for (int ma = 0; ma < 2; ma++)
                #pragma unroll
                for (int na = 0; na < 8; na++) mma_bf16(acc[ma][na], ah[ma], bh[na]);
            #pragma unroll
            for (int ma = 0; ma < 2; ma++)
                #pragma unroll
                for (int na = 0; na < 8; na++) mma_bf16(acc[ma][na], ah[ma], bl[na]);
            #pragma unroll
            for (int ma = 0; ma < 2; ma++)
                #pragma unroll
                for (int na = 0; na < 8; na++) mma_bf16(acc[ma][na], al[ma], bh[na]);
        }

        __syncthreads();
        if (i + 2 < nk) load_stage(i & 1, (i + 2) * BKE);
        else CP_COMMIT();   // keep group accounting uniform
    }

    // ===================== epilogue =====================
    const int gq = lane >> 2, rq = lane & 3;
    #pragma unroll
    for (int ma = 0; ma < 2; ma++) {
        #pragma unroll
        for (int half = 0; half < 2; half++) {
            const long row = tileM + wm * 32 + ma * 16 + gq + half * 8;
            #pragma unroll
            for (int na = 0; na < 8; na++) {
                const long col = tileN + wn * 64 + na * 8 + rq * 2;
                float v0 = acc[ma][na][half * 2 + 0] * alpha;
                float v1 = acc[ma][na][half * 2 + 1] * alpha;
                if (bias) { v0 += bias[z * sBias + col]; v1 += bias[z * sBias + col + 1]; }
                if (csc)  { v0 *= csc[z * sCsc + col];   v1 *= csc[z * sCsc + col + 1]; }
                if (OUT == 0) {
                    float2 f2; f2.x = v0; f2.y = v1;
                    *(float2*)(Cf + z * sC + row * ldc + col) = f2;
                } else {
                    const __nv_bfloat16 h0 = __float2bfloat16(v0);
                    const __nv_bfloat16 h1 = __float2bfloat16(v1);
                    const __nv_bfloat16 l0 = __float2bfloat16(v0 - __bfloat162float(h0));
                    const __nv_bfloat16 l1 = __float2bfloat16(v1 - __bfloat162float(h1));
                    __nv_bfloat162 hp; hp.x = h0; hp.y = h1;
                    __nv_bfloat162 lp; lp.x = l0; lp.y = l1;
                    *(__nv_bfloat162*)(Ch + z * sC + row * ldc + col) = hp;
                    *(__nv_bfloat162*)(Cl + z * sC + row * ldc + col) = lp;
                }
            }
        }
    }
}

// ===================== elementwise fp32 -> bf16 hi/lo split =====================
__global__ __launch_bounds__(256)
void split_kernel(const float* __restrict__ X, __nv_bfloat16* __restrict__ Xh,
                  __nv_bfloat16* __restrict__ Xl)
{
    const long i = ((long)blockIdx.x * 256 + threadIdx.x) * 4;
    const float4 f = *(const float4*)(X + i);
    float v[4] = {f.x, f.y, f.z, f.w};
    __nv_bfloat16 h[4], l[4];
    #pragma unroll
    for (int k = 0; k < 4; k++) {
        h[k] = __float2bfloat16(v[k]);
        l[k] = __float2bfloat16(v[k] - __bfloat162float(h[k]));
    }
    *(uint2*)(Xh + i) = *(const uint2*)h;
    *(uint2*)(Xl + i) = *(const uint2*)l;
}

// ===================== pack bias / IA3 scale buffers (once per replay) ============
__global__ __launch_bounds__(256)
void pack_biascsc(const float* __restrict__ bq, const float* __restrict__ bk,
                  const float* __restrict__ bv, const float* __restrict__ lk,
                  const float* __restrict__ lv,
                  float* __restrict__ biasP, float* __restrict__ cscP)
{
    const int i = blockIdx.x * 256 + threadIdx.x;   // over L_*D_ = 9216 (exact)
    biasP[0 * L_ * D_ + i] = bq[i];
    biasP[1 * L_ * D_ + i] = bk[i];
    biasP[2 * L_ * D_ + i] = bv[i];
    cscP [0 * L_ * D_ + i] = 1.0f;
    cscP [1 * L_ * D_ + i] = lk[i];
    cscP [2 * L_ * D_ + i] = lv[i];
}

// ===================== batched transpose + split: fp32 X(R,C) -> T(C,R) hi/lo =========
__global__ void transpose_split(const float* __restrict__ X,
                                __nv_bfloat16* __restrict__ Th, __nv_bfloat16* __restrict__ Tl,
                                int R, int C, long sX, long sT)
{
    __shared__ float t[32][33];
    const int z = blockIdx.z;
    X  += z * sX;
    Th += z * sT;
    Tl += z * sT;
    const int c0 = blockIdx.x * 32, r0 = blockIdx.y * 32;
    const int tx = threadIdx.x, ty = threadIdx.y;
    #pragma unroll
    for (int k = 0; k < 4; k++)
        t[ty + 8*k][tx] = X[(long)(r0 + ty + 8*k) * C + c0 + tx];
    __syncthreads();
    #pragma unroll
    for (int k = 0; k < 4; k++) {
        const float v = t[tx][ty + 8*k];
        const long o = (long)(c0 + ty + 8*k) * R + r0 + tx;
        const __nv_bfloat16 h = __float2bfloat16(v);
        Th[o] = h;
        Tl[o] = __float2bfloat16(v - __bfloat162float(h));
    }
}

// ===================== batched transpose + re-split from bf16 pair ===================
__global__ void transpose_split2(const __nv_bfloat16* __restrict__ Xh,
                                 const __nv_bfloat16* __restrict__ Xl,
                                 __nv_bfloat16* __restrict__ Th, __nv_bfloat16* __restrict__ Tl,
                                 int R, int C, long sX, long sT)
{
    __shared__ float t[32][33];
    const int z = blockIdx.z;
    Xh += z * sX;
    Xl += z * sX;
    Th += z * sT;
    Tl += z * sT;
    const int c0 = blockIdx.x * 32, r0 = blockIdx.y * 32;
    const int tx = threadIdx.x, ty = threadIdx.y;
    #pragma unroll
    for (int k = 0; k < 4; k++) {
        const long o = (long)(r0 + ty + 8*k) * C + c0 + tx;
        t[ty + 8*k][tx] = __bfloat162float(Xh[o]) + __bfloat162float(Xl[o]);
    }
    __syncthreads();
    #pragma unroll
    for (int k = 0; k < 4; k++) {
        const float v = t[tx][ty + 8*k];
        const long o = (long)(c0 + ty + 8*k) * R + r0 + tx;
        const __nv_bfloat16 h = __float2bfloat16(v);
        Th[o] = h;
        Tl[o] = __float2bfloat16(v - __bfloat162float(h));
    }
}

// ===================== row softmax: fp32 in -> bf16 hi/lo out =====================
__global__ __launch_bounds__(256)
void softmax_split(const float* __restrict__ P,
                   __nv_bfloat16* __restrict__ Ph, __nv_bfloat16* __restrict__ Pl)
{
    const long row = blockIdx.x;
    const int tid = threadIdx.x;
    __shared__ float red[8];

    const float4 f = *(const float4*)(P + row * S_ + tid * 4);
    float v[4] = {f.x, f.y, f.z, f.w};

    float m = fmaxf(fmaxf(v[0], v[1]), fmaxf(v[2], v[3]));
    #pragma unroll
    for (int o = 16; o; o >>= 1) m = fmaxf(m, __shfl_xor_sync(0xFFFFFFFFu, m, o));
    if ((tid & 31) == 0) red[tid >> 5] = m;
    __syncthreads();
    if (tid < 8) {
        float t = red[tid];
        #pragma unroll
        for (int o = 4; o; o >>= 1) t = fmaxf(t, __shfl_xor_sync(0xFFu, t, o));
        if (tid == 0) red[0] = t;
    }
    __syncthreads();
    m = red[0];
    __syncthreads();

    float s = 0.f;
    #pragma unroll
    for (int k = 0; k < 4; k++) { v[k] = __expf(v[k] - m); s += v[k]; }
    #pragma unroll
    for (int o = 16; o; o >>= 1) s += __shfl_xor_sync(0xFFFFFFFFu, s, o);
    if ((tid & 31) == 0) red[tid >> 5] = s;
    __syncthreads();
    if (tid < 8) {
        float t = red[tid];
        #pragma unroll
        for (int o = 4; o; o >>= 1) t += __shfl_xor_sync(0xFFu, t, o);
        if (tid == 0) red[0] = t;
    }
    __syncthreads();
    const float inv = 1.f / red[0];

    __nv_bfloat16 h[4], l[4];
    #pragma unroll
    for (int k = 0; k < 4; k++) {
        const float p = v[k] * inv;
        h[k] = __float2bfloat16(p);
        l[k] = __float2bfloat16(p - __bfloat162float(h[k]));
    }
    *(uint2*)(Ph + row * S_ + tid * 4) = *(const uint2*)h;
    *(uint2*)(Pl + row * S_ + tid * 4) = *(const uint2*)l;
}

// ===================== head: out[b] = (hh+hl)[b,0,:] . W_head + b_head =====================
__global__ __launch_bounds__(256)
void head_kernel(const __nv_bfloat16* __restrict__ hh, const __nv_bfloat16* __restrict__ hl,
                 const float* __restrict__ Wh, const float* __restrict__ bh,
                 float* __restrict__ out)
{
    const int b = blockIdx.x;
    const long base = (long)b * S_ * D_;
    const int tid = threadIdx.x;
    __shared__ float red[8];

    float s = 0.f;
    for (int d = tid; d < D_; d += 256)
        s += (__bfloat162float(hh[base + d]) + __bfloat162float(hl[base + d])) * Wh[d];
    #pragma unroll
    for (int o = 16; o; o >>= 1) s += __shfl_xor_sync(0xFFFFFFFFu, s, o);
    if ((tid & 31) == 0) red[tid >> 5] = s;
    __syncthreads();
    if (tid == 0) {
        float t = 0.f;
        #pragma unroll
        for (int w = 0; w < 8; w++) t += red[w];
        out[b] = t + bh[0];
    }
}

// ===================== driver =====================
extern "C" void kernel_launch(void* const* d_in, const int* in_sizes, int n_in,
                              void* d_out, int out_size)
{
    const float* hs    = (const float*)d_in[0];
    const float* Wq    = (const float*)d_in[1];
    const float* bq    = (const float*)d_in[2];
    const float* Wk    = (const float*)d_in[3];
    const float* bk    = (const float*)d_in[4];
    const float* Wv    = (const float*)d_in[5];
    const float* bv    = (const float*)d_in[6];
    const float* lk    = (const float*)d_in[7];
    const float* lv    = (const float*)d_in[8];
    const float* Whead = (const float*)d_in[9];
    const float* bhead = (const float*)d_in[10];
    float* out = (float*)d_out;

    __nv_bfloat16 *hh, *hl, *QKVh, *QKVl, *Vth, *Vtl, *Ph, *Pl, *Wth, *Wtl;
    float *P, *biasP, *cscP;
    cudaGetSymbolAddress((void**)&hh,   g_hh);   cudaGetSymbolAddress((void**)&hl,   g_hl);
    cudaGetSymbolAddress((void**)&QKVh, g_QKVh); cudaGetSymbolAddress((void**)&QKVl, g_QKVl);
    cudaGetSymbolAddress((void**)&Vth,  g_Vth);  cudaGetSymbolAddress((void**)&Vtl,  g_Vtl);
    cudaGetSymbolAddress((void**)&P,    g_P);
    cudaGetSymbolAddress((void**)&Ph,   g_Ph);   cudaGetSymbolAddress((void**)&Pl,   g_Pl);
    cudaGetSymbolAddress((void**)&Wth,  g_Wth);  cudaGetSymbolAddress((void**)&Wtl,  g_Wtl);
    cudaGetSymbolAddress((void**)&biasP, g_biasP);
    cudaGetSymbolAddress((void**)&cscP,  g_cscP);

    cudaFuncSetAttribute(gemm_mma<0>, cudaFuncAttributeMaxDynamicSharedMemorySize, GEMM_SMEM);
    cudaFuncSetAttribute(gemm_mma<1>, cudaFuncAttributeMaxDynamicSharedMemorySize, GEMM_SMEM);

    const float attn_alpha = 1.0f / sqrtf((float)D_);
    const long SD  = (long)S_ * D_;
    const long SS  = (long)S_ * S_;
    const long DD  = (long)D_ * D_;
    const long LD  = (long)L_ * D_;
    const long LDD = (long)L_ * DD;

    // initial split of hidden states; pack bias/csc
    split_kernel<<<(B_ * S_ * D_) / (256 * 4), 256>>>(hs, hh, hl);
    pack_biascsc<<<(L_ * D_) / 256, 256>>>(bq, bk, bv, lk, lv, biasP, cscP);

    // weights: (K,N) -> (N,K) transposed bf16 split, into packed slabs [w][L][D][D]
    {
        const dim3 tb(32, 8);
        const dim3 tg(D_ / 32, D_ / 32, L_);
        transpose_split<<<tg, tb>>>(Wq, Wth + 0*LDD, Wtl + 0*LDD, D_, D_, DD, DD);
        transpose_split<<<tg, tb>>>(Wk, Wth + 1*LDD, Wtl + 1*LDD, D_, D_, DD, DD);
        transpose_split<<<tg, tb>>>(Wv, Wth + 2*LDD, Wtl + 2*LDD, D_, D_, DD, DD);
    }

    const dim3 blk(256);
    const dim3 grid_qkv(D_ / BN, (B_ * S_) / BM, 3);    // (6, 256, 3) merged Q,K,V
    const dim3 grid_qk(S_ / BN, S_ / BM, B_);           // (8, 8, 32)
    const dim3 grid_pv(D_ / BN, S_ / BM, B_);           // (6, 8, 32)

    for (int l = 0; l < L_; l++) {
        const long wo = (long)l * DD;

        // merged: {Q,K,V} = h @ {Wq,Wk,Wv} + {bq,bk,bv}, scaled {1,lk,lv} -> split bf16 slabs
        gemm_mma<1><<<grid_qkv, blk, GEMM_SMEM>>>(
            hh, hl, Wth + wo, Wtl + wo, nullptr, QKVh, QKVl,
            biasP + (long)l * D_, cscP + (long)l * D_, 1.0f,
            D_, D_, D_, D_, 0, LDD, (long)SDW, LD, LD);

        // V (slab 2, B,S,D) -> Vt (B,D,S) re-split
        transpose_split2<<<dim3(D_ / 32, S_ / 32, B_), dim3(32, 8)>>>(
            QKVh + 2 * SDW, QKVl + 2 * SDW, Vth, Vtl, S_, D_, SD, SD);

        // P = alpha * Q @ K^T -> fp32 (batched)
        gemm_mma<0><<<grid_qk, blk, GEMM_SMEM>>>(
            QKVh, QKVl, QKVh + SDW, QKVl + SDW, P, nullptr, nullptr,
            nullptr, nullptr, attn_alpha, D_, D_, D_, S_, SD, SD, SS, 0, 0);

        // softmax rows -> split bf16
        softmax_split<<<B_ * S_, blk>>>(P, Ph, Pl);

        // h = P @ V  (= P @ Vt^T) -> split bf16 (batched)
        gemm_mma<1><<<grid_pv, blk, GEMM_SMEM>>>(
            Ph, Pl, Vth, Vtl, nullptr, hh, hl,
            nullptr, nullptr, 1.0f, S_, S_, S_, D_, SS, SD, SD, 0, 0);
    }

    head_kernel<<<B_, blk>>>(hh, hl, Whead, bhead, out);
}

// round 11
// speedup vs baseline: 2.2805x; 1.0014x over previous
#include <cuda_runtime.h>
#include <cuda_bf16.h>
#include <math.h>
#include <stdint.h>

#define B_ 32
#define S_ 1024
#define D_ 768
#define L_ 12
#define SDW ((size_t)B_*S_*D_)

// ===================== scratch (__device__ globals; no allocs) =====================
__device__ __align__(16) __nv_bfloat16 g_hh  [(size_t)B_*S_*D_];
__device__ __align__(16) __nv_bfloat16 g_hl  [(size_t)B_*S_*D_];
__device__ __align__(16) __nv_bfloat16 g_QKVh[(size_t)3*B_*S_*D_];   // slabs: Q,K,V
__device__ __align__(16) __nv_bfloat16 g_QKVl[(size_t)3*B_*S_*D_];
__device__ __align__(16) __nv_bfloat16 g_Vth [(size_t)B_*S_*D_];     // (B, D, S)
__device__ __align__(16) __nv_bfloat16 g_Vtl [(size_t)B_*S_*D_];
__device__ __align__(16) float         g_P   [(size_t)B_*S_*S_];
__device__ __align__(16) __nv_bfloat16 g_Ph  [(size_t)B_*S_*S_];
__device__ __align__(16) __nv_bfloat16 g_Pl  [(size_t)B_*S_*S_];
__device__ __align__(16) __nv_bfloat16 g_Wth [(size_t)3*L_*D_*D_];   // slabs: Wq,Wk,Wv (N,K)
__device__ __align__(16) __nv_bfloat16 g_Wtl [(size_t)3*L_*D_*D_];
__device__ float g_biasP[(size_t)3*L_*D_];   // packed bq,bk,bv
__device__ float g_cscP [(size_t)3*L_*D_];   // packed 1, lk, lv

// ===================== PTX helpers (generic sm_80+ features only) =====================
__device__ __forceinline__ uint32_t smem_u32(const void* p) {
    uint32_t a;
    asm("{ .reg .u64 t; cvta.to.shared.u64 t, %1; cvt.u32.u64 %0, t; }" : "=r"(a) : "l"(p));
    return a;
}
__device__ __forceinline__ void cpa16(uint32_t s, const void* g) {
    asm volatile("cp.async.cg.shared.global [%0], [%1], 16;" :: "r"(s), "l"(g));
}
#define CP_COMMIT() asm volatile("cp.async.commit_group;" ::: "memory")
#define CP_WAIT1()  asm volatile("cp.async.wait_group 1;" ::: "memory")

__device__ __forceinline__ void ldm_x4(uint32_t& r0, uint32_t& r1, uint32_t& r2, uint32_t& r3,
                                       uint32_t a) {
    asm volatile("ldmatrix.sync.aligned.m8n8.x4.shared.b16 {%0,%1,%2,%3}, [%4];"
                 : "=r"(r0), "=r"(r1), "=r"(r2), "=r"(r3) : "r"(a));
}
__device__ __forceinline__ void mma_bf16(float* c, const uint32_t* a, const uint32_t* b) {
    asm volatile("mma.sync.aligned.m16n8k16.row.col.f32.bf16.bf16.f32 "
                 "{%0,%1,%2,%3}, {%4,%5,%6,%7}, {%8,%9}, {%0,%1,%2,%3};"
                 : "+f"(c[0]), "+f"(c[1]), "+f"(c[2]), "+f"(c[3])
                 : "r"(a[0]), "r"(a[1]), "r"(a[2]), "r"(a[3]), "r"(b[0]), "r"(b[1]));
}

// ===================== GEMM: C[M,N] = alpha * (A @ Bt^T) (+bias[z])(*csc[z]) =========
// A: [M,K] row-major split (Ah,Al).  Bt: [N,K] row-major split (Bh,Bl).
// bf16x3: acc += AhBh + AhBl + AlBh  (fp32 accum).
// OUT=0: fp32 C.  OUT=1: bf16 hi/lo split (Ch, Cl).
#define BM 128
#define BN 128
#define BKE 32                       // K elems per stage
#define ROWB 80                      // padded row bytes (32 bf16 = 64B + 16B pad)
#define TILEB (128 * ROWB)           // 10240 B per tile
#define STAGEB (4 * TILEB)           // Ah, Al, Bh, Bl = 40960 B
#define GEMM_SMEM (2 * STAGEB)       // 81920 B

template<int OUT>
__global__ __launch_bounds__(256, 2)
void gemm_mma(const __nv_bfloat16* __restrict__ Ah, const __nv_bfloat16* __restrict__ Al,
              const __nv_bfloat16* __restrict__ Bh, const __nv_bfloat16* __restrict__ Bl,
              float* __restrict__ Cf,
              __nv_bfloat16* __restrict__ Ch, __nv_bfloat16* __restrict__ Cl,
              const float* __restrict__ bias, const float* __restrict__ csc,
              float alpha, int K, int lda, int ldb, int ldc,
              long sA, long sB, long sC, long sBias, long sCsc)
{
    extern __shared__ char smem[];
    const uint32_t sbase = smem_u32(smem);
    const int tid = threadIdx.x;
    const int lane = tid & 31, wid = tid >> 5;
    const int wm = wid & 3, wn = wid >> 2;          // 4 (M) x 2 (N) warps
    const int z = blockIdx.z;
    Ah += z * sA;  Al += z * sA;
    Bh += z * sB;  Bl += z * sB;

    const long tileM = blockIdx.y * (long)BM;
    const long tileN = blockIdx.x * (long)BN;

    const __nv_bfloat16* gAh = Ah + tileM * lda;
    const __nv_bfloat16* gAl = Al + tileM * lda;
    const __nv_bfloat16* gBh = Bh + tileN * ldb;
    const __nv_bfloat16* gBl = Bl + tileN * ldb;

    // per-thread load slots: 128 rows x 4 chunks (16B) = 512 slots, 2 per thread
    const int r0q = tid >> 2, c0q = tid & 3;

    auto load_stage = [&](int stage, int k0) {
        const uint32_t sb = sbase + stage * STAGEB;
        #pragma unroll
        for (int it = 0; it < 2; it++) {
            const int r = r0q + it * 64;
            const long go = (long)r * lda + k0 + c0q * 8;
            const long gb = (long)r * ldb + k0 + c0q * 8;
            const uint32_t so = r * ROWB + c0q * 16;
            cpa16(sb + 0 * TILEB + so, gAh + go);
            cpa16(sb + 1 * TILEB + so, gAl + go);
            cpa16(sb + 2 * TILEB + so, gBh + gb);
            cpa16(sb + 3 * TILEB + so, gBl + gb);
        }
        CP_COMMIT();
    };

    float acc[2][8][4];
    #pragma unroll
    for (int i = 0; i < 2; i++)
        #pragma unroll
        for (int j = 0; j < 8; j++)
            #pragma unroll
            for (int q = 0; q < 4; q++) acc[i][j][q] = 0.f;

    const int nk = K / BKE;
    load_stage(0, 0);
    load_stage(1, BKE);

    // ldmatrix per-thread address components
    const int a_row  = wm * 32 + (lane & 15);                          // + ma*16
    const int b_row  = wn * 64 + (lane & 7) + ((lane >> 3) & 1) * 8;   // + nb*16
    const int colb   = (lane >> 4) * 16;                               // + ks*32

    for (int i = 0; i < nk; i++) {
        CP_WAIT1();
        __syncthreads();
        const uint32_t sb = sbase + (i & 1) * STAGEB;

        #pragma unroll
        for (int ks = 0; ks < 2; ks++) {
            uint32_t ah[2][4], al[2][4], bh[8][2], bl[8][2];
            #pragma unroll
            for (int ma = 0; ma < 2; ma++) {
                const uint32_t ad = sb + (a_row + ma * 16) * ROWB + ks * 32 + colb;
                ldm_x4(ah[ma][0], ah[ma][1], ah[ma][2], ah[ma][3], ad);
                ldm_x4(al[ma][0], al[ma][1], al[ma][2], al[ma][3], ad + TILEB);
            }
            #pragma unroll
            for (int nb = 0; nb < 4; nb++) {
                const uint32_t bd = sb + 2 * TILEB + (b_row + nb * 16) * ROWB + ks * 32 + colb;
                uint32_t t0, t1, t2, t3;
                ldm_x4(t0, t1, t2, t3, bd);
                bh[2*nb][0] = t0; bh[2*nb][1] = t2; bh[2*nb+1][0] = t1; bh[2*nb+1][1] = t3;
                ldm_x4(t0, t1, t2, t3, bd + TILEB);
                bl[2*nb][0] = t0; bl[2*nb][1] = t2; bl[2*nb+1][0] = t1; bl[2*nb+1][1] = t3;
            }
            // product-major ordering: 16 independent accs between dependent MMAs
            #pragma unroll
            for (int ma = 0; ma < 2; ma++)
                #pragma unroll
                for (int na = 0; na < 8; na++) mma_bf16(acc[ma][na], ah[ma], bh[na]);
            #pragma unroll
            for (int ma = 0; ma < 2; ma++)
                #pragma unroll
                for (int na = 0; na < 8; na++) mma_bf16(acc[ma][na], ah[ma], bl[na]);
            #pragma unroll
            for (int ma = 0; ma < 2; ma++)
                #pragma unroll
                for (int na = 0; na < 8; na++) mma_bf16(acc[ma][na], al[ma], bh[na]);
        }

        __syncthreads();
        if (i + 2 < nk) load_stage(i & 1, (i + 2) * BKE);
        else CP_COMMIT();   // keep group accounting uniform
    }

    // ===================== epilogue =====================
    const int gq = lane >> 2, rq = lane & 3;
    #pragma unroll
    for (int ma = 0; ma < 2; ma++) {
        #pragma unroll
        for (int half = 0; half < 2; half++) {
            const long row = tileM + wm * 32 + ma * 16 + gq + half * 8;
            #pragma unroll
            for (int na = 0; na < 8; na++) {
                const long col = tileN + wn * 64 + na * 8 + rq * 2;
                float v0 = acc[ma][na][half * 2 + 0] * alpha;
                float v1 = acc[ma][na][half * 2 + 1] * alpha;
                if (bias) { v0 += bias[z * sBias + col]; v1 += bias[z * sBias + col + 1]; }
                if (csc)  { v0 *= csc[z * sCsc + col];   v1 *= csc[z * sCsc + col + 1]; }
                if (OUT == 0) {
                    float2 f2; f2.x = v0; f2.y = v1;
                    *(float2*)(Cf + z * sC + row * ldc + col) = f2;
                } else {
                    const __nv_bfloat16 h0 = __float2bfloat16(v0);
                    const __nv_bfloat16 h1 = __float2bfloat16(v1);
                    const __nv_bfloat16 l0 = __float2bfloat16(v0 - __bfloat162float(h0));
                    const __nv_bfloat16 l1 = __float2bfloat16(v1 - __bfloat162float(h1));
                    __nv_bfloat162 hp; hp.x = h0; hp.y = h1;
                    __nv_bfloat162 lp; lp.x = l0; lp.y = l1;
                    *(__nv_bfloat162*)(Ch + z * sC + row * ldc + col) = hp;
                    *(__nv_bfloat162*)(Cl + z * sC + row * ldc + col) = lp;
                }
            }
        }
    }
}

// ===================== elementwise fp32 -> bf16 hi/lo split =====================
__global__ __launch_bounds__(256)
void split_kernel(const float* __restrict__ X, __nv_bfloat16* __restrict__ Xh,
                  __nv_bfloat16* __restrict__ Xl)
{
    const long i = ((long)blockIdx.x * 256 + threadIdx.x) * 4;
    const float4 f = *(const float4*)(X + i);
    float v[4] = {f.x, f.y, f.z, f.w};
    __nv_bfloat16 h[4], l[4];
    #pragma unroll
    for (int k = 0; k < 4; k++) {
        h[k] = __float2bfloat16(v[k]);
        l[k] = __float2bfloat16(v[k] - __bfloat162float(h[k]));
    }
    *(uint2*)(Xh + i) = *(const uint2*)h;
    *(uint2*)(Xl + i) = *(const uint2*)l;
}

// ===================== pack bias / IA3 scale buffers (once per replay) ============
__global__ __launch_bounds__(256)
void pack_biascsc(const float* __restrict__ bq, const float* __restrict__ bk,
                  const float* __restrict__ bv, const float* __restrict__ lk,
                  const float* __restrict__ lv,
                  float* __restrict__ biasP, float* __restrict__ cscP)
{
    const int i = blockIdx.x * 256 + threadIdx.x;   // over L_*D_ = 9216 (exact)
    biasP[0 * L_ * D_ + i] = bq[i];
    biasP[1 * L_ * D_ + i] = bk[i];
    biasP[2 * L_ * D_ + i] = bv[i];
    cscP [0 * L_ * D_ + i] = 1.0f;
    cscP [1 * L_ * D_ + i] = lk[i];
    cscP [2 * L_ * D_ + i] = lv[i];
}

// ===================== batched transpose + split: fp32 X(R,C) -> T(C,R) hi/lo =========
__global__ void transpose_split(const float* __restrict__ X,
                                __nv_bfloat16* __restrict__ Th, __nv_bfloat16* __restrict__ Tl,
                                int R, int C, long sX, long sT)
{
    __shared__ float t[32][33];
    const int z = blockIdx.z;
    X  += z * sX;
    Th += z * sT;
    Tl += z * sT;
    const int c0 = blockIdx.x * 32, r0 = blockIdx.y * 32;
    const int tx = threadIdx.x, ty = threadIdx.y;
    #pragma unroll
    for (int k = 0; k < 4; k++)
        t[ty + 8*k][tx] = X[(long)(r0 + ty + 8*k) * C + c0 + tx];
    __syncthreads();
    #pragma unroll
    for (int k = 0; k < 4; k++) {
        const float v = t[tx][ty + 8*k];
        const long o = (long)(c0 + ty + 8*k) * R + r0 + tx;
        const __nv_bfloat16 h = __float2bfloat16(v);
        Th[o] = h;
        Tl[o] = __float2bfloat16(v - __bfloat162float(h));
    }
}

// ===================== batched transpose + re-split from bf16 pair ===================
__global__ void transpose_split2(const __nv_bfloat16* __restrict__ Xh,
                                 const __nv_bfloat16* __restrict__ Xl,
                                 __nv_bfloat16* __restrict__ Th, __nv_bfloat16* __restrict__ Tl,
                                 int R, int C, long sX, long sT)
{
    __shared__ float t[32][33];
    const int z = blockIdx.z;
    Xh += z * sX;
    Xl += z * sX;
    Th += z * sT;
    Tl += z * sT;
    const int c0 = blockIdx.x * 32, r0 = blockIdx.y * 32;
    const int tx = threadIdx.x, ty = threadIdx.y;
    #pragma unroll
    for (int k = 0; k < 4; k++) {
        const long o = (long)(r0 + ty + 8*k) * C + c0 + tx;
        t[ty + 8*k][tx] = __bfloat162float(Xh[o]) + __bfloat162float(Xl[o]);
    }
    __syncthreads();
    #pragma unroll
    for (int k = 0; k < 4; k++) {
        const float v = t[tx][ty + 8*k];
        const long o = (long)(c0 + ty + 8*k) * R + r0 + tx;
        const __nv_bfloat16 h = __float2bfloat16(v);
        Th[o] = h;
        Tl[o] = __float2bfloat16(v - __bfloat162float(h));
    }
}

// ===================== row softmax: fp32 in -> bf16 hi/lo out =====================
__global__ __launch_bounds__(256)
void softmax_split(const float* __restrict__ P,
                   __nv_bfloat16* __restrict__ Ph, __nv_bfloat16* __restrict__ Pl)
{
    const long row = blockIdx.x;
    const int tid = threadIdx.x;
    __shared__ float red[8];

    const float4 f = *(const float4*)(P + row * S_ + tid * 4);
    float v[4] = {f.x, f.y, f.z, f.w};

    float m = fmaxf(fmaxf(v[0], v[1]), fmaxf(v[2], v[3]));
    #pragma unroll
    for (int o = 16; o; o >>= 1) m = fmaxf(m, __shfl_xor_sync(0xFFFFFFFFu, m, o));
    if ((tid & 31) == 0) red[tid >> 5] = m;
    __syncthreads();
    if (tid < 8) {
        float t = red[tid];
        #pragma unroll
        for (int o = 4; o; o >>= 1) t = fmaxf(t, __shfl_xor_sync(0xFFu, t, o));
        if (tid == 0) red[0] = t;
    }
    __syncthreads();
    m = red[0];
    __syncthreads();

    float s = 0.f;
    #pragma unroll
    for (int k = 0; k < 4; k++) { v[k] = __expf(v[k] - m); s += v[k]; }
    #pragma unroll
    for (int o = 16; o; o >>= 1) s += __shfl_xor_sync(0xFFFFFFFFu, s, o);
    if ((tid & 31) == 0) red[tid >> 5] = s;
    __syncthreads();
    if (tid < 8) {
        float t = red[tid];
        #pragma unroll
        for (int o = 4; o; o >>= 1) t += __shfl_xor_sync(0xFFu, t, o);
        if (tid == 0) red[0] = t;
    }
    __syncthreads();
    const float inv = 1.f / red[0];

    __nv_bfloat16 h[4], l[4];
    #pragma unroll
    for (int k = 0; k < 4; k++) {
        const float p = v[k] * inv;
        h[k] = __float2bfloat16(p);
        l[k] = __float2bfloat16(p - __bfloat162float(h[k]));
    }
    *(uint2*)(Ph + row * S_ + tid * 4) = *(const uint2*)h;
    *(uint2*)(Pl + row * S_ + tid * 4) = *(const uint2*)l;
}

// ===================== head: out[b] = (hh+hl)[b,0,:] . W_head + b_head =====================
__global__ __launch_bounds__(256)
void head_kernel(const __nv_bfloat16* __restrict__ hh, const __nv_bfloat16* __restrict__ hl,
                 const float* __restrict__ Wh, const float* __restrict__ bh,
                 float* __restrict__ out)
{
    const int b = blockIdx.x;
    const long base = (long)b * S_ * D_;
    const int tid = threadIdx.x;
    __shared__ float red[8];

    float s = 0.f;
    for (int d = tid; d < D_; d += 256)
        s += (__bfloat162float(hh[base + d]) + __bfloat162float(hl[base + d])) * Wh[d];
    #pragma unroll
    for (int o = 16; o; o >>= 1) s += __shfl_xor_sync(0xFFFFFFFFu, s, o);
    if ((tid & 31) == 0) red[tid >> 5] = s;
    __syncthreads();
    if (tid == 0) {
        float t = 0.f;
        #pragma unroll
        for (int w = 0; w < 8; w++) t += red[w];
        out[b] = t + bh[0];
    }
}

// ===================== driver =====================
extern "C" void kernel_launch(void* const* d_in, const int* in_sizes, int n_in,
                              void* d_out, int out_size)
{
    const float* hs    = (const float*)d_in[0];
    const float* Wq    = (const float*)d_in[1];
    const float* bq    = (const float*)d_in[2];
    const float* Wk    = (const float*)d_in[3];
    const float* bk    = (const float*)d_in[4];
    const float* Wv    = (const float*)d_in[5];
    const float* bv    = (const float*)d_in[6];
    const float* lk    = (const float*)d_in[7];
    const float* lv    = (const float*)d_in[8];
    const float* Whead = (const float*)d_in[9];
    const float* bhead = (const float*)d_in[10];
    float* out = (float*)d_out;

    __nv_bfloat16 *hh, *hl, *QKVh, *QKVl, *Vth, *Vtl, *Ph, *Pl, *Wth, *Wtl;
    float *P, *biasP, *cscP;
    cudaGetSymbolAddress((void**)&hh,   g_hh);   cudaGetSymbolAddress((void**)&hl,   g_hl);
    cudaGetSymbolAddress((void**)&QKVh, g_QKVh); cudaGetSymbolAddress((void**)&QKVl, g_QKVl);
    cudaGetSymbolAddress((void**)&Vth,  g_Vth);  cudaGetSymbolAddress((void**)&Vtl,  g_Vtl);
    cudaGetSymbolAddress((void**)&P,    g_P);
    cudaGetSymbolAddress((void**)&Ph,   g_Ph);   cudaGetSymbolAddress((void**)&Pl,   g_Pl);
    cudaGetSymbolAddress((void**)&Wth,  g_Wth);  cudaGetSymbolAddress((void**)&Wtl,  g_Wtl);
    cudaGetSymbolAddress((void**)&biasP, g_biasP);
    cudaGetSymbolAddress((void**)&cscP,  g_cscP);

    cudaFuncSetAttribute(gemm_mma<0>, cudaFuncAttributeMaxDynamicSharedMemorySize, GEMM_SMEM);
    cudaFuncSetAttribute(gemm_mma<1>, cudaFuncAttributeMaxDynamicSharedMemorySize, GEMM_SMEM);

    // side stream + events for fork/join under graph capture (host objects only;
    // created per call — kernel_launch runs once for correctness + once for capture)
    cudaStream_t s2;
    cudaStreamCreateWithFlags(&s2, cudaStreamNonBlocking);
    cudaEvent_t evFork[L_ + 1], evJoin[L_ + 1];
    for (int i = 0; i <= L_; i++) {
        cudaEventCreateWithFlags(&evFork[i], cudaEventDisableTiming);
        cudaEventCreateWithFlags(&evJoin[i], cudaEventDisableTiming);
    }

    const float attn_alpha = 1.0f / sqrtf((float)D_);
    const long SD  = (long)S_ * D_;
    const long SS  = (long)S_ * S_;
    const long DD  = (long)D_ * D_;
    const long LD  = (long)L_ * D_;
    const long LDD = (long)L_ * DD;

    const dim3 blk(256);

    // ---- prep: fork weight transposes + packing onto s2, h split on main ----
    cudaEventRecord(evFork[L_], 0);
    cudaStreamWaitEvent(s2, evFork[L_], 0);
    {
        const dim3 tb(32, 8);
        const dim3 tg(D_ / 32, D_ / 32, L_);
        transpose_split<<<tg, tb, 0, s2>>>(Wq, Wth + 0*LDD, Wtl + 0*LDD, D_, D_, DD, DD);
        transpose_split<<<tg, tb, 0, s2>>>(Wk, Wth + 1*LDD, Wtl + 1*LDD, D_, D_, DD, DD);
        transpose_split<<<tg, tb, 0, s2>>>(Wv, Wth + 2*LDD, Wtl + 2*LDD, D_, D_, DD, DD);
        pack_biascsc<<<(L_ * D_) / 256, 256, 0, s2>>>(bq, bk, bv, lk, lv, biasP, cscP);
    }
    cudaEventRecord(evJoin[L_], s2);
    split_kernel<<<(B_ * S_ * D_) / (256 * 4), blk>>>(hs, hh, hl);
    cudaStreamWaitEvent(0, evJoin[L_], 0);

    const dim3 grid_qkv(D_ / BN, (B_ * S_) / BM, 3);    // (6, 256, 3) merged Q,K,V
    const dim3 grid_qk(S_ / BN, S_ / BM, B_);           // (8, 8, 32)
    const dim3 grid_pv(D_ / BN, S_ / BM, B_);           // (6, 8, 32)

    for (int l = 0; l < L_; l++) {
        const long wo = (long)l * DD;

        // merged: {Q,K,V} = h @ {Wq,Wk,Wv} + {bq,bk,bv}, scaled {1,lk,lv} -> split bf16 slabs
        gemm_mma<1><<<grid_qkv, blk, GEMM_SMEM>>>(
            hh, hl, Wth + wo, Wtl + wo, nullptr, QKVh, QKVl,
            biasP + (long)l * D_, cscP + (long)l * D_, 1.0f,
            D_, D_, D_, D_, 0, LDD, (long)SDW, LD, LD);

        // fork: V transpose on s2, concurrent with QK + softmax on main
        cudaEventRecord(evFork[l], 0);
        cudaStreamWaitEvent(s2, evFork[l], 0);
        transpose_split2<<<dim3(D_ / 32, S_ / 32, B_), dim3(32, 8), 0, s2>>>(
            QKVh + 2 * SDW, QKVl + 2 * SDW, Vth, Vtl, S_, D_, SD, SD);
        cudaEventRecord(evJoin[l], s2);

        // P = alpha * Q @ K^T -> fp32 (batched)
        gemm_mma<0><<<grid_qk, blk, GEMM_SMEM>>>(
            QKVh, QKVl, QKVh + SDW, QKVl + SDW, P, nullptr, nullptr,
            nullptr, nullptr, attn_alpha, D_, D_, D_, S_, SD, SD, SS, 0, 0);

        // softmax rows -> split bf16
        softmax_split<<<B_ * S_, blk>>>(P, Ph, Pl);

        // join: PV needs both softmax (main) and Vt (s2)
        cudaStreamWaitEvent(0, evJoin[l], 0);

        // h = P @ V  (= P @ Vt^T) -> split bf16 (batched)
        gemm_mma<1><<<grid_pv, blk, GEMM_SMEM>>>(
            Ph, Pl, Vth, Vtl, nullptr, hh, hl,
            nullptr, nullptr, 1.0f, S_, S_, S_, D_, SS, SD, SD, 0, 0);
    }

    head_kernel<<<B_, blk>>>(hh, hl, Whead, bhead, out);
}

// round 12
// speedup vs baseline: 2.3679x; 1.0383x over previous
#include <cuda_runtime.h>
#include <cuda_bf16.h>
#include <math.h>
#include <stdint.h>

#define B_ 32
#define S_ 1024
#define D_ 768
#define L_ 12
#define SDW ((size_t)B_*S_*D_)

// ===================== scratch (__device__ globals; no allocs) =====================
__device__ __align__(16) __nv_bfloat16 g_hh  [(size_t)B_*S_*D_];
__device__ __align__(16) __nv_bfloat16 g_hl  [(size_t)B_*S_*D_];
__device__ __align__(16) __nv_bfloat16 g_QKVh[(size_t)3*B_*S_*D_];   // slabs: Q,K,V
__device__ __align__(16) __nv_bfloat16 g_QKVl[(size_t)3*B_*S_*D_];
__device__ __align__(16) float         g_P   [(size_t)B_*S_*S_];
__device__ __align__(16) __nv_bfloat16 g_Ph  [(size_t)B_*S_*S_];
__device__ __align__(16) __nv_bfloat16 g_Pl  [(size_t)B_*S_*S_];
__device__ __align__(16) __nv_bfloat16 g_Wth [(size_t)3*L_*D_*D_];   // slabs: Wq,Wk,Wv (N,K)
__device__ __align__(16) __nv_bfloat16 g_Wtl [(size_t)3*L_*D_*D_];
__device__ float g_biasP[(size_t)3*L_*D_];   // packed bq,bk,bv
__device__ float g_cscP [(size_t)3*L_*D_];   // packed 1, lk, lv

// ===================== PTX helpers (generic sm_80+ features only) =====================
__device__ __forceinline__ uint32_t smem_u32(const void* p) {
    uint32_t a;
    asm("{ .reg .u64 t; cvta.to.shared.u64 t, %1; cvt.u32.u64 %0, t; }" : "=r"(a) : "l"(p));
    return a;
}
__device__ __forceinline__ void cpa16(uint32_t s, const void* g) {
    asm volatile("cp.async.cg.shared.global [%0], [%1], 16;" :: "r"(s), "l"(g));
}
#define CP_COMMIT() asm volatile("cp.async.commit_group;" ::: "memory")
#define CP_WAIT1()  asm volatile("cp.async.wait_group 1;" ::: "memory")

__device__ __forceinline__ void ldm_x4(uint32_t& r0, uint32_t& r1, uint32_t& r2, uint32_t& r3,
                                       uint32_t a) {
    asm volatile("ldmatrix.sync.aligned.m8n8.x4.shared.b16 {%0,%1,%2,%3}, [%4];"
                 : "=r"(r0), "=r"(r1), "=r"(r2), "=r"(r3) : "r"(a));
}
__device__ __forceinline__ void ldm_x4t(uint32_t& r0, uint32_t& r1, uint32_t& r2, uint32_t& r3,
                                        uint32_t a) {
    asm volatile("ldmatrix.sync.aligned.m8n8.x4.trans.shared.b16 {%0,%1,%2,%3}, [%4];"
                 : "=r"(r0), "=r"(r1), "=r"(r2), "=r"(r3) : "r"(a));
}
__device__ __forceinline__ void mma_bf16(float* c, const uint32_t* a, const uint32_t* b) {
    asm volatile("mma.sync.aligned.m16n8k16.row.col.f32.bf16.bf16.f32 "
                 "{%0,%1,%2,%3}, {%4,%5,%6,%7}, {%8,%9}, {%0,%1,%2,%3};"
                 : "+f"(c[0]), "+f"(c[1]), "+f"(c[2]), "+f"(c[3])
                 : "r"(a[0]), "r"(a[1]), "r"(a[2]), "r"(a[3]), "r"(b[0]), "r"(b[1]));
}

// ===================== GEMM ==============
// BTRANS=0: Bt [N,K] row-major (NT).   BTRANS=1: B [K,N] row-major (NN, trans-ldmatrix).
// A: [M,K] row-major split (Ah,Al).  bf16x3: acc += AhBh + AhBl + AlBh (fp32 accum).
// OUT=0: fp32 C.  OUT=1: bf16 hi/lo split (Ch, Cl).
#define BM 128
#define BN 128
#define BKE 32                        // K elems per stage
#define ROWB 80                       // A/NT-B padded row bytes (64B + 16B pad)
#define TILEB (128 * ROWB)            // 10240 B
#define BT_ROWB 272                   // NN-B row bytes (256B + 16B pad), 17 units mod 8 = 1
#define BT_TILE (32 * BT_ROWB)        // 8704 B

template<int OUT, int BTRANS>
__global__ __launch_bounds__(256, 2)
void gemm_mma(const __nv_bfloat16* __restrict__ Ah, const __nv_bfloat16* __restrict__ Al,
              const __nv_bfloat16* __restrict__ Bh, const __nv_bfloat16* __restrict__ Bl,
              float* __restrict__ Cf,
              __nv_bfloat16* __restrict__ Ch, __nv_bfloat16* __restrict__ Cl,
              const float* __restrict__ bias, const float* __restrict__ csc,
              float alpha, int K, int lda, int ldb, int ldc,
              long sA, long sB, long sC, long sBias, long sCsc)
{
    constexpr int BTILEB = BTRANS ? BT_TILE : TILEB;
    constexpr int STAGEB = 2 * TILEB + 2 * BTILEB;

    extern __shared__ char smem[];
    const uint32_t sbase = smem_u32(smem);
    const int tid = threadIdx.x;
    const int lane = tid & 31, wid = tid >> 5;
    const int wm = wid & 3, wn = wid >> 2;          // 4 (M) x 2 (N) warps
    const int z = blockIdx.z;
    Ah += z * sA;  Al += z * sA;
    Bh += z * sB;  Bl += z * sB;

    const long tileM = blockIdx.y * (long)BM;
    const long tileN = blockIdx.x * (long)BN;

    const __nv_bfloat16* gAh = Ah + tileM * lda;
    const __nv_bfloat16* gAl = Al + tileM * lda;
    const __nv_bfloat16* gBh = BTRANS ? Bh : (Bh + tileN * ldb);
    const __nv_bfloat16* gBl = BTRANS ? Bl : (Bl + tileN * ldb);

    // A load slots: 128 rows x 4 chunks (16B) = 512, 2/thread
    const int r0q = tid >> 2, c0q = tid & 3;
    // NN-B load slots: 32 rows x 16 chunks (16B) = 512, 2/thread
    const int rB = tid >> 4, cB = tid & 15;

    auto load_stage = [&](int stage, int k0) {
        const uint32_t sb = sbase + stage * STAGEB;
        #pragma unroll
        for (int it = 0; it < 2; it++) {
            const int r = r0q + it * 64;
            const long go = (long)r * lda + k0 + c0q * 8;
            const uint32_t so = r * ROWB + c0q * 16;
            cpa16(sb + 0 * TILEB + so, gAh + go);
            cpa16(sb + 1 * TILEB + so, gAl + go);
        }
        if (BTRANS) {
            #pragma unroll
            for (int it = 0; it < 2; it++) {
                const int idx = tid + it * 256;
                const int r = idx >> 4, c = idx & 15;
                const long go = (long)(k0 + r) * ldb + tileN + c * 8;
                const uint32_t so = r * BT_ROWB + c * 16;
                cpa16(sb + 2 * TILEB + so, gBh + go);
                cpa16(sb + 2 * TILEB + BTILEB + so, gBl + go);
            }
        } else {
            #pragma unroll
            for (int it = 0; it < 2; it++) {
                const int r = r0q + it * 64;
                const long gb = (long)r * ldb + k0 + c0q * 8;
                const uint32_t so = r * ROWB + c0q * 16;
                cpa16(sb + 2 * TILEB + so, gBh + gb);
                cpa16(sb + 2 * TILEB + BTILEB + so, gBl + gb);
            }
        }
        CP_COMMIT();
    };

    float acc[2][8][4];
    #pragma unroll
    for (int i = 0; i < 2; i++)
        #pragma unroll
        for (int j = 0; j < 8; j++)
            #pragma unroll
            for (int q = 0; q < 4; q++) acc[i][j][q] = 0.f;

    const int nk = K / BKE;
    load_stage(0, 0);
    load_stage(1, BKE);

    // ldmatrix per-thread address components
    const int a_row  = wm * 32 + (lane & 15);                          // + ma*16
    const int b_row  = wn * 64 + (lane & 7) + ((lane >> 3) & 1) * 8;   // NT: + nb*16
    const int colb   = (lane >> 4) * 16;                               // + ks*32
    // NN (trans): k row within tile + n column
    const int bt_k   = ((lane >> 4) & 1) * 8 + (lane & 7);             // + ks*16
    const int bt_n   = wn * 64 + ((lane >> 3) & 1) * 8;                // + nb*16

    for (int i = 0; i < nk; i++) {
        CP_WAIT1();
        __syncthreads();
        const uint32_t sb = sbase + (i & 1) * STAGEB;

        #pragma unroll
        for (int ks = 0; ks < 2; ks++) {
            uint32_t ah[2][4], al[2][4], bh[8][2], bl[8][2];
            #pragma unroll
            for (int ma = 0; ma < 2; ma++) {
                const uint32_t ad = sb + (a_row + ma * 16) * ROWB + ks * 32 + colb;
                ldm_x4(ah[ma][0], ah[ma][1], ah[ma][2], ah[ma][3], ad);
                ldm_x4(al[ma][0], al[ma][1], al[ma][2], al[ma][3], ad + TILEB);
            }
            #pragma unroll
            for (int nb = 0; nb < 4; nb++) {
                uint32_t t0, t1, t2, t3;
                if (BTRANS) {
                    const uint32_t bd = sb + 2 * TILEB
                                      + (ks * 16 + bt_k) * BT_ROWB
                                      + (bt_n + nb * 16) * 2;
                    ldm_x4t(t0, t1, t2, t3, bd);
                    bh[2*nb][0] = t0; bh[2*nb][1] = t2; bh[2*nb+1][0] = t1; bh[2*nb+1][1] = t3;
                    ldm_x4t(t0, t1, t2, t3, bd + BTILEB);
                    bl[2*nb][0] = t0; bl[2*nb][1] = t2; bl[2*nb+1][0] = t1; bl[2*nb+1][1] = t3;
                } else {
                    const uint32_t bd = sb + 2 * TILEB + (b_row + nb * 16) * ROWB + ks * 32 + colb;
                    ldm_x4(t0, t1, t2, t3, bd);
                    bh[2*nb][0] = t0; bh[2*nb][1] = t2; bh[2*nb+1][0] = t1; bh[2*nb+1][1] = t3;
                    ldm_x4(t0, t1, t2, t3, bd + BTILEB);
                    bl[2*nb][0] = t0; bl[2*nb][1] = t2; bl[2*nb+1][0] = t1; bl[2*nb+1][1] = t3;
                }
            }
            // product-major ordering: 16 independent accs between dependent MMAs
            #pragma unroll
            for (int ma = 0; ma < 2; ma++)
                #pragma unroll
                for (int na = 0; na < 8; na++) mma_bf16(acc[ma][na], ah[ma], bh[na]);
            #pragma unroll
            for (int ma = 0; ma < 2; ma++)
                #pragma unroll
                for (int na = 0; na < 8; na++) mma_bf16(acc[ma][na], ah[ma], bl[na]);
            #pragma unroll
            for (int ma = 0; ma < 2; ma++)
                #pragma unroll
                for (int na = 0; na < 8; na++) mma_bf16(acc[ma][na], al[ma], bh[na]);
        }

        __syncthreads();
        if (i + 2 < nk) load_stage(i & 1, (i + 2) * BKE);
        else CP_COMMIT();   // keep group accounting uniform
    }

    // ===================== epilogue =====================
    const int gq = lane >> 2, rq = lane & 3;
    #pragma unroll
    for (int ma = 0; ma < 2; ma++) {
        #pragma unroll
        for (int half = 0; half < 2; half++) {
            const long row = tileM + wm * 32 + ma * 16 + gq + half * 8;
            #pragma unroll
            for (int na = 0; na < 8; na++) {
                const long col = tileN + wn * 64 + na * 8 + rq * 2;
                float v0 = acc[ma][na][half * 2 + 0] * alpha;
                float v1 = acc[ma][na][half * 2 + 1] * alpha;
                if (bias) { v0 += bias[z * sBias + col]; v1 += bias[z * sBias + col + 1]; }
                if (csc)  { v0 *= csc[z * sCsc + col];   v1 *= csc[z * sCsc + col + 1]; }
                if (OUT == 0) {
                    float2 f2; f2.x = v0; f2.y = v1;
                    *(float2*)(Cf + z * sC + row * ldc + col) = f2;
                } else {
                    const __nv_bfloat16 h0 = __float2bfloat16(v0);
                    const __nv_bfloat16 h1 = __float2bfloat16(v1);
                    const __nv_bfloat16 l0 = __float2bfloat16(v0 - __bfloat162float(h0));
                    const __nv_bfloat16 l1 = __float2bfloat16(v1 - __bfloat162float(h1));
                    __nv_bfloat162 hp; hp.x = h0; hp.y = h1;
                    __nv_bfloat162 lp; lp.x = l0; lp.y = l1;
                    *(__nv_bfloat162*)(Ch + z * sC + row * ldc + col) = hp;
                    *(__nv_bfloat162*)(Cl + z * sC + row * ldc + col) = lp;
                }
            }
        }
    }
}

#define GEMM_SMEM_NT (2 * (2 * TILEB + 2 * TILEB))     // 81920
#define GEMM_SMEM_NN (2 * (2 * TILEB + 2 * BT_TILE))   // 75776

// ===================== elementwise fp32 -> bf16 hi/lo split =====================
__global__ __launch_bounds__(256)
void split_kernel(const float* __restrict__ X, __nv_bfloat16* __restrict__ Xh,
                  __nv_bfloat16* __restrict__ Xl)
{
    const long i = ((long)blockIdx.x * 256 + threadIdx.x) * 4;
    const float4 f = *(const float4*)(X + i);
    float v[4] = {f.x, f.y, f.z, f.w};
    __nv_bfloat16 h[4], l[4];
    #pragma unroll
    for (int k = 0; k < 4; k++) {
        h[k] = __float2bfloat16(v[k]);
        l[k] = __float2bfloat16(v[k] - __bfloat162float(h[k]));
    }
    *(uint2*)(Xh + i) = *(const uint2*)h;
    *(uint2*)(Xl + i) = *(const uint2*)l;
}

// ===================== pack bias / IA3 scale buffers (once per replay) ============
__global__ __launch_bounds__(256)
void pack_biascsc(const float* __restrict__ bq, const float* __restrict__ bk,
                  const float* __restrict__ bv, const float* __restrict__ lk,
                  const float* __restrict__ lv,
                  float* __restrict__ biasP, float* __restrict__ cscP)
{
    const int i = blockIdx.x * 256 + threadIdx.x;   // over L_*D_ = 9216 (exact)
    biasP[0 * L_ * D_ + i] = bq[i];
    biasP[1 * L_ * D_ + i] = bk[i];
    biasP[2 * L_ * D_ + i] = bv[i];
    cscP [0 * L_ * D_ + i] = 1.0f;
    cscP [1 * L_ * D_ + i] = lk[i];
    cscP [2 * L_ * D_ + i] = lv[i];
}

// ===================== batched transpose + split: fp32 X(R,C) -> T(C,R) hi/lo =========
__global__ void transpose_split(const float* __restrict__ X,
                                __nv_bfloat16* __restrict__ Th, __nv_bfloat16* __restrict__ Tl,
                                int R, int C, long sX, long sT)
{
    __shared__ float t[32][33];
    const int z = blockIdx.z;
    X  += z * sX;
    Th += z * sT;
    Tl += z * sT;
    const int c0 = blockIdx.x * 32, r0 = blockIdx.y * 32;
    const int tx = threadIdx.x, ty = threadIdx.y;
    #pragma unroll
    for (int k = 0; k < 4; k++)
        t[ty + 8*k][tx] = X[(long)(r0 + ty + 8*k) * C + c0 + tx];
    __syncthreads();
    #pragma unroll
    for (int k = 0; k < 4; k++) {
        const float v = t[tx][ty + 8*k];
        const long o = (long)(c0 + ty + 8*k) * R + r0 + tx;
        const __nv_bfloat16 h = __float2bfloat16(v);
        Th[o] = h;
        Tl[o] = __float2bfloat16(v - __bfloat162float(h));
    }
}

// ===================== row softmax: fp32 in -> bf16 hi/lo out =====================
__global__ __launch_bounds__(256)
void softmax_split(const float* __restrict__ P,
                   __nv_bfloat16* __restrict__ Ph, __nv_bfloat16* __restrict__ Pl)
{
    const long row = blockIdx.x;
    const int tid = threadIdx.x;
    __shared__ float red[8];

    const float4 f = *(const float4*)(P + row * S_ + tid * 4);
    float v[4] = {f.x, f.y, f.z, f.w};

    float m = fmaxf(fmaxf(v[0], v[1]), fmaxf(v[2], v[3]));
    #pragma unroll
    for (int o = 16; o; o >>= 1) m = fmaxf(m, __shfl_xor_sync(0xFFFFFFFFu, m, o));
    if ((tid & 31) == 0) red[tid >> 5] = m;
    __syncthreads();
    if (tid < 8) {
        float t = red[tid];
        #pragma unroll
        for (int o = 4; o; o >>= 1) t = fmaxf(t, __shfl_xor_sync(0xFFu, t, o));
        if (tid == 0) red[0] = t;
    }
    __syncthreads();
    m = red[0];
    __syncthreads();

    float s = 0.f;
    #pragma unroll
    for (int k = 0; k < 4; k++) { v[k] = __expf(v[k] - m); s += v[k]; }
    #pragma unroll
    for (int o = 16; o; o >>= 1) s += __shfl_xor_sync(0xFFFFFFFFu, s, o);
    if ((tid & 31) == 0) red[tid >> 5] = s;
    __syncthreads();
    if (tid < 8) {
        float t = red[tid];
        #pragma unroll
        for (int o = 4; o; o >>= 1) t += __shfl_xor_sync(0xFFu, t, o);
        if (tid == 0) red[0] = t;
    }
    __syncthreads();
    const float inv = 1.f / red[0];

    __nv_bfloat16 h[4], l[4];
    #pragma unroll
    for (int k = 0; k < 4; k++) {
        const float p = v[k] * inv;
        h[k] = __float2bfloat16(p);
        l[k] = __float2bfloat16(p - __bfloat162float(h[k]));
    }
    *(uint2*)(Ph + row * S_ + tid * 4) = *(const uint2*)h;
    *(uint2*)(Pl + row * S_ + tid * 4) = *(const uint2*)l;
}

// ===================== head: out[b] = (hh+hl)[b,0,:] . W_head + b_head =====================
__global__ __launch_bounds__(256)
void head_kernel(const __nv_bfloat16* __restrict__ hh, const __nv_bfloat16* __restrict__ hl,
                 const float* __restrict__ Wh, const float* __restrict__ bh,
                 float* __restrict__ out)
{
    const int b = blockIdx.x;
    const long base = (long)b * S_ * D_;
    const int tid = threadIdx.x;
    __shared__ float red[8];

    float s = 0.f;
    for (int d = tid; d < D_; d += 256)
        s += (__bfloat162float(hh[base + d]) + __bfloat162float(hl[base + d])) * Wh[d];
    #pragma unroll
    for (int o = 16; o; o >>= 1) s += __shfl_xor_sync(0xFFFFFFFFu, s, o);
    if ((tid & 31) == 0) red[tid >> 5] = s;
    __syncthreads();
    if (tid == 0) {
        float t = 0.f;
        #pragma unroll
        for (int w = 0; w < 8; w++) t += red[w];
        out[b] = t + bh[0];
    }
}

// ===================== driver =====================
extern "C" void kernel_launch(void* const* d_in, const int* in_sizes, int n_in,
                              void* d_out, int out_size)
{
    const float* hs    = (const float*)d_in[0];
    const float* Wq    = (const float*)d_in[1];
    const float* bq    = (const float*)d_in[2];
    const float* Wk    = (const float*)d_in[3];
    const float* bk    = (const float*)d_in[4];
    const float* Wv    = (const float*)d_in[5];
    const float* bv    = (const float*)d_in[6];
    const float* lk    = (const float*)d_in[7];
    const float* lv    = (const float*)d_in[8];
    const float* Whead = (const float*)d_in[9];
    const float* bhead = (const float*)d_in[10];
    float* out = (float*)d_out;

    __nv_bfloat16 *hh, *hl, *QKVh, *QKVl, *Ph, *Pl, *Wth, *Wtl;
    float *P, *biasP, *cscP;
    cudaGetSymbolAddress((void**)&hh,   g_hh);   cudaGetSymbolAddress((void**)&hl,   g_hl);
    cudaGetSymbolAddress((void**)&QKVh, g_QKVh); cudaGetSymbolAddress((void**)&QKVl, g_QKVl);
    cudaGetSymbolAddress((void**)&P,    g_P);
    cudaGetSymbolAddress((void**)&Ph,   g_Ph);   cudaGetSymbolAddress((void**)&Pl,   g_Pl);
    cudaGetSymbolAddress((void**)&Wth,  g_Wth);  cudaGetSymbolAddress((void**)&Wtl,  g_Wtl);
    cudaGetSymbolAddress((void**)&biasP, g_biasP);
    cudaGetSymbolAddress((void**)&cscP,  g_cscP);

    cudaFuncSetAttribute((const void*)gemm_mma<0,0>, cudaFuncAttributeMaxDynamicSharedMemorySize, GEMM_SMEM_NT);
    cudaFuncSetAttribute((const void*)gemm_mma<1,0>, cudaFuncAttributeMaxDynamicSharedMemorySize, GEMM_SMEM_NT);
    cudaFuncSetAttribute((const void*)gemm_mma<1,1>, cudaFuncAttributeMaxDynamicSharedMemorySize, GEMM_SMEM_NN);

    const float attn_alpha = 1.0f / sqrtf((float)D_);
    const long SD  = (long)S_ * D_;
    const long SS  = (long)S_ * S_;
    const long DD  = (long)D_ * D_;
    const long LD  = (long)L_ * D_;
    const long LDD = (long)L_ * DD;

    const dim3 blk(256);

    // ---- prep ----
    split_kernel<<<(B_ * S_ * D_) / (256 * 4), blk>>>(hs, hh, hl);
    pack_biascsc<<<(L_ * D_) / 256, 256>>>(bq, bk, bv, lk, lv, biasP, cscP);
    {
        const dim3 tb(32, 8);
        const dim3 tg(D_ / 32, D_ / 32, L_);
        transpose_split<<<tg, tb>>>(Wq, Wth + 0*LDD, Wtl + 0*LDD, D_, D_, DD, DD);
        transpose_split<<<tg, tb>>>(Wk, Wth + 1*LDD, Wtl + 1*LDD, D_, D_, DD, DD);
        transpose_split<<<tg, tb>>>(Wv, Wth + 2*LDD, Wtl + 2*LDD, D_, D_, DD, DD);
    }

    const dim3 grid_qkv(D_ / BN, (B_ * S_) / BM, 3);    // (6, 256, 3) merged Q,K,V
    const dim3 grid_qk(S_ / BN, S_ / BM, B_);           // (8, 8, 32)
    const dim3 grid_pv(D_ / BN, S_ / BM, B_);           // (6, 8, 32)

    for (int l = 0; l < L_; l++) {
        const long wo = (long)l * DD;

        // merged: {Q,K,V} = h @ {Wq,Wk,Wv} + {bq,bk,bv}, scaled {1,lk,lv} -> split bf16 slabs
        gemm_mma<1,0><<<grid_qkv, blk, GEMM_SMEM_NT>>>(
            hh, hl, Wth + wo, Wtl + wo, nullptr, QKVh, QKVl,
            biasP + (long)l * D_, cscP + (long)l * D_, 1.0f,
            D_, D_, D_, D_, 0, LDD, (long)SDW, LD, LD);

        // P = alpha * Q @ K^T -> fp32 (batched, NT)
        gemm_mma<0,0><<<grid_qk, blk, GEMM_SMEM_NT>>>(
            QKVh, QKVl, QKVh + SDW, QKVl + SDW, P, nullptr, nullptr,
            nullptr, nullptr, attn_alpha, D_, D_, D_, S_, SD, SD, SS, 0, 0);

        // softmax rows -> split bf16
        softmax_split<<<B_ * S_, blk>>>(P, Ph, Pl);

        // h = P @ V  (NN: V slab [S,D] used directly via trans-ldmatrix)
        gemm_mma<1,1><<<grid_pv, blk, GEMM_SMEM_NN>>>(
            Ph, Pl, QKVh + 2 * SDW, QKVl + 2 * SDW, nullptr, hh, hl,
            nullptr, nullptr, 1.0f, S_, S_, D_, D_, SS, SD, SD, 0, 0);
    }

    head_kernel<<<B_, blk>>>(hh, hl, Whead, bhead, out);
}

// round 13
// speedup vs baseline: 2.8111x; 1.1872x over previous
#include <cuda_runtime.h>
#include <cuda_bf16.h>
#include <math.h>
#include <stdint.h>

#define B_ 32
#define S_ 1024
#define D_ 768
#define L_ 12
#define MTOT (B_*S_)
#define NAUG 1664                    // [M(768) | w1 | w2 | pad(126) | Wv(768)]
#define VOFF 896
#define LB ((long)D_*NAUG)           // per-layer Baug stride
#define SDW ((size_t)B_*S_*D_)
#define SGV ((size_t)B_*S_*NAUG)

// ===================== scratch (__device__ globals; no allocs) =====================
__device__ __align__(16) __nv_bfloat16 g_hh  [(size_t)MTOT*D_];
__device__ __align__(16) __nv_bfloat16 g_hl  [(size_t)MTOT*D_];
__device__ __align__(16) __nv_bfloat16 g_GVh [(size_t)MTOT*NAUG];   // [G | u | w | pad | V]
__device__ __align__(16) __nv_bfloat16 g_GVl [(size_t)MTOT*NAUG];
__device__ __align__(16) float         g_P   [(size_t)B_*S_*S_];
__device__ __align__(16) __nv_bfloat16 g_Ph  [(size_t)B_*S_*S_];
__device__ __align__(16) __nv_bfloat16 g_Pl  [(size_t)B_*S_*S_];
__device__ __align__(16) __nv_bfloat16 g_Baugh[(size_t)L_*D_*NAUG];
__device__ __align__(16) __nv_bfloat16 g_Baugl[(size_t)L_*D_*NAUG];
__device__ __align__(16) __nv_bfloat16 g_Wqsh[(size_t)L_*D_*D_];    // Wq split (straight)
__device__ __align__(16) __nv_bfloat16 g_Wqsl[(size_t)L_*D_*D_];
__device__ __align__(16) __nv_bfloat16 g_Wksh[(size_t)L_*D_*D_];    // Wk*lk split
__device__ __align__(16) __nv_bfloat16 g_Wksl[(size_t)L_*D_*D_];
__device__ float g_biasVG[(size_t)L_*NAUG];
__device__ float g_cscVG [(size_t)L_*NAUG];
__device__ float g_U[MTOT];
__device__ float g_W[MTOT];
__device__ float g_c[L_];

// ===================== PTX helpers (generic sm_80+ features only) =====================
__device__ __forceinline__ uint32_t smem_u32(const void* p) {
    uint32_t a;
    asm("{ .reg .u64 t; cvta.to.shared.u64 t, %1; cvt.u32.u64 %0, t; }" : "=r"(a) : "l"(p));
    return a;
}
__device__ __forceinline__ void cpa16(uint32_t s, const void* g) {
    asm volatile("cp.async.cg.shared.global [%0], [%1], 16;" :: "r"(s), "l"(g));
}
#define CP_COMMIT() asm volatile("cp.async.commit_group;" ::: "memory")
#define CP_WAIT1()  asm volatile("cp.async.wait_group 1;" ::: "memory")

__device__ __forceinline__ void ldm_x4(uint32_t& r0, uint32_t& r1, uint32_t& r2, uint32_t& r3,
                                       uint32_t a) {
    asm volatile("ldmatrix.sync.aligned.m8n8.x4.shared.b16 {%0,%1,%2,%3}, [%4];"
                 : "=r"(r0), "=r"(r1), "=r"(r2), "=r"(r3) : "r"(a));
}
__device__ __forceinline__ void ldm_x4t(uint32_t& r0, uint32_t& r1, uint32_t& r2, uint32_t& r3,
                                        uint32_t a) {
    asm volatile("ldmatrix.sync.aligned.m8n8.x4.trans.shared.b16 {%0,%1,%2,%3}, [%4];"
                 : "=r"(r0), "=r"(r1), "=r"(r2), "=r"(r3) : "r"(a));
}
__device__ __forceinline__ void mma_bf16(float* c, const uint32_t* a, const uint32_t* b) {
    asm volatile("mma.sync.aligned.m16n8k16.row.col.f32.bf16.bf16.f32 "
                 "{%0,%1,%2,%3}, {%4,%5,%6,%7}, {%8,%9}, {%0,%1,%2,%3};"
                 : "+f"(c[0]), "+f"(c[1]), "+f"(c[2]), "+f"(c[3])
                 : "r"(a[0]), "r"(a[1]), "r"(a[2]), "r"(a[3]), "r"(b[0]), "r"(b[1]));
}

// ===================== GEMM ==============
// BTRANS=0: Bt [N,K] row-major (NT).   BTRANS=1: B [K,N] row-major (NN, trans-ldmatrix).
// A: [M,K] row-major split (Ah,Al).  bf16x3: acc += AhBh + AhBl + AlBh (fp32 accum).
// OUT=0: fp32 C.  OUT=1: bf16 hi/lo split (Ch, Cl).
#define BM 128
#define BN 128
#define BKE 32
#define ROWB 80
#define TILEB (128 * ROWB)            // 10240 B
#define BT_ROWB 272                   // 256B + 16B pad; 17 units mod 8 = 1
#define BT_TILE (32 * BT_ROWB)        // 8704 B

template<int OUT, int BTRANS>
__global__ __launch_bounds__(256, 2)
void gemm_mma(const __nv_bfloat16* __restrict__ Ah, const __nv_bfloat16* __restrict__ Al,
              const __nv_bfloat16* __restrict__ Bh, const __nv_bfloat16* __restrict__ Bl,
              float* __restrict__ Cf,
              __nv_bfloat16* __restrict__ Ch, __nv_bfloat16* __restrict__ Cl,
              const float* __restrict__ bias, const float* __restrict__ csc,
              float alpha, int K, int lda, int ldb, int ldc,
              long sA, long sB, long sC)
{
    constexpr int BTILEB = BTRANS ? BT_TILE : TILEB;
    constexpr int STAGEB = 2 * TILEB + 2 * BTILEB;

    extern __shared__ char smem[];
    const uint32_t sbase = smem_u32(smem);
    const int tid = threadIdx.x;
    const int lane = tid & 31, wid = tid >> 5;
    const int wm = wid & 3, wn = wid >> 2;
    const int z = blockIdx.z;
    Ah += z * sA;  Al += z * sA;
    Bh += z * sB;  Bl += z * sB;

    const long tileM = blockIdx.y * (long)BM;
    const long tileN = blockIdx.x * (long)BN;

    const __nv_bfloat16* gAh = Ah + tileM * lda;
    const __nv_bfloat16* gAl = Al + tileM * lda;
    const __nv_bfloat16* gBh = BTRANS ? Bh : (Bh + tileN * ldb);
    const __nv_bfloat16* gBl = BTRANS ? Bl : (Bl + tileN * ldb);

    const int r0q = tid >> 2, c0q = tid & 3;

    auto load_stage = [&](int stage, int k0) {
        const uint32_t sb = sbase + stage * STAGEB;
        #pragma unroll
        for (int it = 0; it < 2; it++) {
            const int r = r0q + it * 64;
            const long go = (long)r * lda + k0 + c0q * 8;
            const uint32_t so = r * ROWB + c0q * 16;
            cpa16(sb + 0 * TILEB + so, gAh + go);
            cpa16(sb + 1 * TILEB + so, gAl + go);
        }
        if (BTRANS) {
            #pragma unroll
            for (int it = 0; it < 2; it++) {
                const int idx = tid + it * 256;
                const int r = idx >> 4, c = idx & 15;
                const long go = (long)(k0 + r) * ldb + tileN + c * 8;
                const uint32_t so = r * BT_ROWB + c * 16;
                cpa16(sb + 2 * TILEB + so, gBh + go);
                cpa16(sb + 2 * TILEB + BTILEB + so, gBl + go);
            }
        } else {
            #pragma unroll
            for (int it = 0; it < 2; it++) {
                const int r = r0q + it * 64;
                const long gb = (long)r * ldb + k0 + c0q * 8;
                const uint32_t so = r * ROWB + c0q * 16;
                cpa16(sb + 2 * TILEB + so, gBh + gb);
                cpa16(sb + 2 * TILEB + BTILEB + so, gBl + gb);
            }
        }
        CP_COMMIT();
    };

    float acc[2][8][4];
    #pragma unroll
    for (int i = 0; i < 2; i++)
        #pragma unroll
        for (int j = 0; j < 8; j++)
            #pragma unroll
            for (int q = 0; q < 4; q++) acc[i][j][q] = 0.f;

    const int nk = K / BKE;
    load_stage(0, 0);
    load_stage(1, BKE);

    const int a_row  = wm * 32 + (lane & 15);
    const int b_row  = wn * 64 + (lane & 7) + ((lane >> 3) & 1) * 8;
    const int colb   = (lane >> 4) * 16;
    const int bt_k   = ((lane >> 4) & 1) * 8 + (lane & 7);
    const int bt_n   = wn * 64 + ((lane >> 3) & 1) * 8;

    for (int i = 0; i < nk; i++) {
        CP_WAIT1();
        __syncthreads();
        const uint32_t sb = sbase + (i & 1) * STAGEB;

        #pragma unroll
        for (int ks = 0; ks < 2; ks++) {
            uint32_t ah[2][4], al[2][4], bh[8][2], bl[8][2];
            #pragma unroll
            for (int ma = 0; ma < 2; ma++) {
                const uint32_t ad = sb + (a_row + ma * 16) * ROWB + ks * 32 + colb;
                ldm_x4(ah[ma][0], ah[ma][1], ah[ma][2], ah[ma][3], ad);
                ldm_x4(al[ma][0], al[ma][1], al[ma][2], al[ma][3], ad + TILEB);
            }
            #pragma unroll
            for (int nb = 0; nb < 4; nb++) {
                uint32_t t0, t1, t2, t3;
                if (BTRANS) {
                    const uint32_t bd = sb + 2 * TILEB
                                      + (ks * 16 + bt_k) * BT_ROWB
                                      + (bt_n + nb * 16) * 2;
                    ldm_x4t(t0, t1, t2, t3, bd);
                    bh[2*nb][0] = t0; bh[2*nb][1] = t2; bh[2*nb+1][0] = t1; bh[2*nb+1][1] = t3;
                    ldm_x4t(t0, t1, t2, t3, bd + BTILEB);
                    bl[2*nb][0] = t0; bl[2*nb][1] = t2; bl[2*nb+1][0] = t1; bl[2*nb+1][1] = t3;
                } else {
                    const uint32_t bd = sb + 2 * TILEB + (b_row + nb * 16) * ROWB + ks * 32 + colb;
                    ldm_x4(t0, t1, t2, t3, bd);
                    bh[2*nb][0] = t0; bh[2*nb][1] = t2; bh[2*nb+1][0] = t1; bh[2*nb+1][1] = t3;
                    ldm_x4(t0, t1, t2, t3, bd + BTILEB);
                    bl[2*nb][0] = t0; bl[2*nb][1] = t2; bl[2*nb+1][0] = t1; bl[2*nb+1][1] = t3;
                }
            }
            #pragma unroll
            for (int ma = 0; ma < 2; ma++)
                #pragma unroll
                for (int na = 0; na < 8; na++) mma_bf16(acc[ma][na], ah[ma], bh[na]);
            #pragma unroll
            for (int ma = 0; ma < 2; ma++)
                #pragma unroll
                for (int na = 0; na < 8; na++) mma_bf16(acc[ma][na], ah[ma], bl[na]);
            #pragma unroll
            for (int ma = 0; ma < 2; ma++)
                #pragma unroll
                for (int na = 0; na < 8; na++) mma_bf16(acc[ma][na], al[ma], bh[na]);
        }

        __syncthreads();
        if (i + 2 < nk) load_stage(i & 1, (i + 2) * BKE);
        else CP_COMMIT();
    }

    // ===================== epilogue =====================
    const int gq = lane >> 2, rq = lane & 3;
    #pragma unroll
    for (int ma = 0; ma < 2; ma++) {
        #pragma unroll
        for (int half = 0; half < 2; half++) {
            const long row = tileM + wm * 32 + ma * 16 + gq + half * 8;
            #pragma unroll
            for (int na = 0; na < 8; na++) {
                const long col = tileN + wn * 64 + na * 8 + rq * 2;
                float v0 = acc[ma][na][half * 2 + 0] * alpha;
                float v1 = acc[ma][na][half * 2 + 1] * alpha;
                if (bias) { v0 += bias[col]; v1 += bias[col + 1]; }
                if (csc)  { v0 *= csc[col];  v1 *= csc[col + 1]; }
                if (OUT == 0) {
                    float2 f2; f2.x = v0; f2.y = v1;
                    *(float2*)(Cf + z * sC + row * ldc + col) = f2;
                } else {
                    const __nv_bfloat16 h0 = __float2bfloat16(v0);
                    const __nv_bfloat16 h1 = __float2bfloat16(v1);
                    const __nv_bfloat16 l0 = __float2bfloat16(v0 - __bfloat162float(h0));
                    const __nv_bfloat16 l1 = __float2bfloat16(v1 - __bfloat162float(h1));
                    __nv_bfloat162 hp; hp.x = h0; hp.y = h1;
                    __nv_bfloat162 lp; lp.x = l0; lp.y = l1;
                    *(__nv_bfloat162*)(Ch + z * sC + row * ldc + col) = hp;
                    *(__nv_bfloat162*)(Cl + z * sC + row * ldc + col) = lp;
                }
            }
        }
    }
}

#define GEMM_SMEM_NT (2 * (2 * TILEB + 2 * TILEB))     // 81920
#define GEMM_SMEM_NN (2 * (2 * TILEB + 2 * BT_TILE))   // 75776

// ===================== elementwise fp32 -> bf16 hi/lo split (contiguous) ============
__global__ __launch_bounds__(256)
void split_kernel(const float* __restrict__ X, __nv_bfloat16* __restrict__ Xh,
                  __nv_bfloat16* __restrict__ Xl)
{
    const long i = ((long)blockIdx.x * 256 + threadIdx.x) * 4;
    const float4 f = *(const float4*)(X + i);
    float v[4] = {f.x, f.y, f.z, f.w};
    __nv_bfloat16 h[4], l[4];
    #pragma unroll
    for (int k = 0; k < 4; k++) {
        h[k] = __float2bfloat16(v[k]);
        l[k] = __float2bfloat16(v[k] - __bfloat162float(h[k]));
    }
    *(uint2*)(Xh + i) = *(const uint2*)h;
    *(uint2*)(Xl + i) = *(const uint2*)l;
}

// ===================== split with optional column scale, strided dst =================
// X: [R,C] fp32 row-major (batched z, stride sX). dst row pitch ldD, column offset off.
__global__ __launch_bounds__(256)
void split_cs(const float* __restrict__ X, const float* __restrict__ sc,
              __nv_bfloat16* __restrict__ Dh, __nv_bfloat16* __restrict__ Dl,
              int C, int ldD, int off, long sX, long sSc, long sD)
{
    const int z = blockIdx.z;
    X += z * sX;
    if (sc) sc += z * sSc;
    Dh += z * sD;
    Dl += z * sD;
    const long idx = ((long)blockIdx.x * 256 + threadIdx.x) * 4;
    const int r = (int)(idx / C), c = (int)(idx % C);
    const float4 f = *(const float4*)(X + idx);
    float v[4] = {f.x, f.y, f.z, f.w};
    __nv_bfloat16 h[4], l[4];
    #pragma unroll
    for (int k = 0; k < 4; k++) {
        const float s = sc ? sc[c + k] : 1.0f;
        const float x = v[k] * s;
        h[k] = __float2bfloat16(x);
        l[k] = __float2bfloat16(x - __bfloat162float(h[k]));
    }
    const long o = (long)r * ldD + off + c;
    *(uint2*)(Dh + o) = *(const uint2*)h;
    *(uint2*)(Dl + o) = *(const uint2*)l;
}

// ===================== pack VG bias / csc =====================
__global__ __launch_bounds__(256)
void pack_vg(const float* __restrict__ bv, const float* __restrict__ lv,
             float* __restrict__ biasVG, float* __restrict__ cscVG)
{
    const int idx = blockIdx.x * 256 + threadIdx.x;    // over L_*NAUG = 19968 (exact)
    const int l = idx / NAUG, c = idx % NAUG;
    biasVG[idx] = (c >= VOFF) ? bv[l * D_ + (c - VOFF)] : 0.0f;
    cscVG[idx]  = (c >= VOFF) ? lv[l * D_ + (c - VOFF)] : 1.0f;
}

// ===================== bias-correction vectors: cols 768/769 of Baug + pad zero ======
__global__ __launch_bounds__(256)
void wvec(const float* __restrict__ Wq, const float* __restrict__ Wk,
          const float* __restrict__ bq, const float* __restrict__ bk,
          const float* __restrict__ lk,
          __nv_bfloat16* __restrict__ Bh, __nv_bfloat16* __restrict__ Bl, float alpha)
{
    const int l = blockIdx.z;
    const int d = blockIdx.x * 256 + threadIdx.x;      // grid.x = 3
    const float* wq = Wq + (long)l * D_ * D_ + (long)d * D_;
    const float* wk = Wk + (long)l * D_ * D_ + (long)d * D_;
    const float* bqz = bq + (long)l * D_;
    const float* bkz = bk + (long)l * D_;
    const float* lkz = lk + (long)l * D_;
    float a1 = 0.f, a2 = 0.f;
    for (int e = 0; e < D_; e++) {
        const float le = lkz[e];
        a1 += wq[e] * le * bkz[e];
        a2 += wk[e] * le * bqz[e];
    }
    a1 *= alpha; a2 *= alpha;
    __nv_bfloat16* bh = Bh + (long)l * LB + (long)d * NAUG;
    __nv_bfloat16* bl = Bl + (long)l * LB + (long)d * NAUG;
    __nv_bfloat16 h = __float2bfloat16(a1);
    bh[768] = h; bl[768] = __float2bfloat16(a1 - __bfloat162float(h));
    h = __float2bfloat16(a2);
    bh[769] = h; bl[769] = __float2bfloat16(a2 - __bfloat162float(h));
    for (int c = 770; c < VOFF; c++) { bh[c] = __float2bfloat16(0.f); bl[c] = __float2bfloat16(0.f); }
}

// ===================== c constant per layer =====================
__global__ __launch_bounds__(256)
void c_kernel(const float* __restrict__ bq, const float* __restrict__ bk,
              const float* __restrict__ lk, float* __restrict__ cOut, float alpha)
{
    const int l = blockIdx.x;
    const int tid = threadIdx.x;
    __shared__ float red[8];
    float s = 0.f;
    for (int e = tid; e < D_; e += 256)
        s += bq[l * D_ + e] * lk[l * D_ + e] * bk[l * D_ + e];
    #pragma unroll
    for (int o = 16; o; o >>= 1) s += __shfl_xor_sync(0xFFFFFFFFu, s, o);
    if ((tid & 31) == 0) red[tid >> 5] = s;
    __syncthreads();
    if (tid == 0) {
        float t = 0.f;
        #pragma unroll
        for (int w = 0; w < 8; w++) t += red[w];
        cOut[l] = alpha * t;
    }
}

// ===================== extract u, w from GV cols 768/769 =====================
__global__ __launch_bounds__(256)
void extract_uw(const __nv_bfloat16* __restrict__ GVh, const __nv_bfloat16* __restrict__ GVl,
                const float* __restrict__ cAll, int l,
                float* __restrict__ U, float* __restrict__ W)
{
    const int i = blockIdx.x * 256 + threadIdx.x;
    const long base = (long)i * NAUG;
    U[i] = __bfloat162float(GVh[base + 768]) + __bfloat162float(GVl[base + 768]) + cAll[l];
    W[i] = __bfloat162float(GVh[base + 769]) + __bfloat162float(GVl[base + 769]);
}

// ===================== row softmax (+u,+w): fp32 in -> bf16 hi/lo out ================
__global__ __launch_bounds__(256)
void softmax_split(const float* __restrict__ P, const float* __restrict__ U,
                   const float* __restrict__ W,
                   __nv_bfloat16* __restrict__ Ph, __nv_bfloat16* __restrict__ Pl)
{
    const long row = blockIdx.x;
    const int tid = threadIdx.x;
    __shared__ float red[8];

    const float4 f = *(const float4*)(P + row * S_ + tid * 4);
    const long wbase = (row >> 10) << 10;              // b * S
    const float4 wv = *(const float4*)(W + wbase + tid * 4);
    const float uv = U[row];
    float v[4] = {f.x + uv + wv.x, f.y + uv + wv.y, f.z + uv + wv.z, f.w + uv + wv.w};

    float m = fmaxf(fmaxf(v[0], v[1]), fmaxf(v[2], v[3]));
    #pragma unroll
    for (int o = 16; o; o >>= 1) m = fmaxf(m, __shfl_xor_sync(0xFFFFFFFFu, m, o));
    if ((tid & 31) == 0) red[tid >> 5] = m;
    __syncthreads();
    if (tid < 8) {
        float t = red[tid];
        #pragma unroll
        for (int o = 4; o; o >>= 1) t = fmaxf(t, __shfl_xor_sync(0xFFu, t, o));
        if (tid == 0) red[0] = t;
    }
    __syncthreads();
    m = red[0];
    __syncthreads();

    float s = 0.f;
    #pragma unroll
    for (int k = 0; k < 4; k++) { v[k] = __expf(v[k] - m); s += v[k]; }
    #pragma unroll
    for (int o = 16; o; o >>= 1) s += __shfl_xor_sync(0xFFFFFFFFu, s, o);
    if ((tid & 31) == 0) red[tid >> 5] = s;
    __syncthreads();
    if (tid < 8) {
        float t = red[tid];
        #pragma unroll
        for (int o = 4; o; o >>= 1) t += __shfl_xor_sync(0xFFu, t, o);
        if (tid == 0) red[0] = t;
    }
    __syncthreads();
    const float inv = 1.f / red[0];

    __nv_bfloat16 h[4], l[4];
    #pragma unroll
    for (int k = 0; k < 4; k++) {
        const float p = v[k] * inv;
        h[k] = __float2bfloat16(p);
        l[k] = __float2bfloat16(p - __bfloat162float(h[k]));
    }
    *(uint2*)(Ph + row * S_ + tid * 4) = *(const uint2*)h;
    *(uint2*)(Pl + row * S_ + tid * 4) = *(const uint2*)l;
}

// ===================== head =====================
__global__ __launch_bounds__(256)
void head_kernel(const __nv_bfloat16* __restrict__ hh, const __nv_bfloat16* __restrict__ hl,
                 const float* __restrict__ Wh, const float* __restrict__ bh,
                 float* __restrict__ out)
{
    const int b = blockIdx.x;
    const long base = (long)b * S_ * D_;
    const int tid = threadIdx.x;
    __shared__ float red[8];

    float s = 0.f;
    for (int d = tid; d < D_; d += 256)
        s += (__bfloat162float(hh[base + d]) + __bfloat162float(hl[base + d])) * Wh[d];
    #pragma unroll
    for (int o = 16; o; o >>= 1) s += __shfl_xor_sync(0xFFFFFFFFu, s, o);
    if ((tid & 31) == 0) red[tid >> 5] = s;
    __syncthreads();
    if (tid == 0) {
        float t = 0.f;
        #pragma unroll
        for (int w = 0; w < 8; w++) t += red[w];
        out[b] = t + bh[0];
    }
}

// ===================== driver =====================
extern "C" void kernel_launch(void* const* d_in, const int* in_sizes, int n_in,
                              void* d_out, int out_size)
{
    const float* hs    = (const float*)d_in[0];
    const float* Wq    = (const float*)d_in[1];
    const float* bq    = (const float*)d_in[2];
    const float* Wk    = (const float*)d_in[3];
    const float* bk    = (const float*)d_in[4];
    const float* Wv    = (const float*)d_in[5];
    const float* bv    = (const float*)d_in[6];
    const float* lk    = (const float*)d_in[7];
    const float* lv    = (const float*)d_in[8];
    const float* Whead = (const float*)d_in[9];
    const float* bhead = (const float*)d_in[10];
    float* out = (float*)d_out;

    __nv_bfloat16 *hh, *hl, *GVh, *GVl, *Ph, *Pl, *Baugh, *Baugl;
    __nv_bfloat16 *Wqsh, *Wqsl, *Wksh, *Wksl;
    float *P, *biasVG, *cscVG, *U, *W, *cArr;
    cudaGetSymbolAddress((void**)&hh,   g_hh);    cudaGetSymbolAddress((void**)&hl,   g_hl);
    cudaGetSymbolAddress((void**)&GVh,  g_GVh);   cudaGetSymbolAddress((void**)&GVl,  g_GVl);
    cudaGetSymbolAddress((void**)&P,    g_P);
    cudaGetSymbolAddress((void**)&Ph,   g_Ph);    cudaGetSymbolAddress((void**)&Pl,   g_Pl);
    cudaGetSymbolAddress((void**)&Baugh, g_Baugh); cudaGetSymbolAddress((void**)&Baugl, g_Baugl);
    cudaGetSymbolAddress((void**)&Wqsh, g_Wqsh);  cudaGetSymbolAddress((void**)&Wqsl, g_Wqsl);
    cudaGetSymbolAddress((void**)&Wksh, g_Wksh);  cudaGetSymbolAddress((void**)&Wksl, g_Wksl);
    cudaGetSymbolAddress((void**)&biasVG, g_biasVG);
    cudaGetSymbolAddress((void**)&cscVG,  g_cscVG);
    cudaGetSymbolAddress((void**)&U,    g_U);     cudaGetSymbolAddress((void**)&W,    g_W);
    cudaGetSymbolAddress((void**)&cArr, g_c);

    cudaFuncSetAttribute((const void*)gemm_mma<0,0>, cudaFuncAttributeMaxDynamicSharedMemorySize, GEMM_SMEM_NT);
    cudaFuncSetAttribute((const void*)gemm_mma<1,0>, cudaFuncAttributeMaxDynamicSharedMemorySize, GEMM_SMEM_NT);
    cudaFuncSetAttribute((const void*)gemm_mma<1,1>, cudaFuncAttributeMaxDynamicSharedMemorySize, GEMM_SMEM_NN);

    const float attn_alpha = 1.0f / sqrtf((float)D_);
    const long SD  = (long)S_ * D_;
    const long SS  = (long)S_ * S_;
    const long DD  = (long)D_ * D_;
    const long SGVl = (long)S_ * NAUG;

    const dim3 blk(256);

    // ================= one-time prep =================
    split_kernel<<<(MTOT * D_) / (256 * 4), blk>>>(hs, hh, hl);
    // straight splits: Wq, Wk*lk (for M-prep); Wv into Baug cols 896..1663
    split_cs<<<dim3(DD / 1024, 1, L_), blk>>>(Wq, nullptr, Wqsh, Wqsl, D_, D_, 0, DD, 0, DD);
    split_cs<<<dim3(DD / 1024, 1, L_), blk>>>(Wk, lk,      Wksh, Wksl, D_, D_, 0, DD, (long)D_, DD);
    split_cs<<<dim3(DD / 1024, 1, L_), blk>>>(Wv, nullptr, Baugh, Baugl, D_, NAUG, VOFF, DD, 0, LB);
    // M = alpha * Wq @ (Wk*lk)^T  -> Baug cols 0..767  (NT, batched over layers)
    gemm_mma<1,0><<<dim3(D_/BN, D_/BM, L_), blk, GEMM_SMEM_NT>>>(
        Wqsh, Wqsl, Wksh, Wksl, nullptr, Baugh, Baugl,
        nullptr, nullptr, attn_alpha, D_, D_, D_, NAUG, DD, DD, LB);
    // bias-correction vectors + pad; c constants; VG bias/csc packs
    wvec<<<dim3(3, 1, L_), blk>>>(Wq, Wk, bq, bk, lk, Baugh, Baugl, attn_alpha);
    c_kernel<<<L_, blk>>>(bq, bk, lk, cArr, attn_alpha);
    pack_vg<<<(L_ * NAUG) / 256, blk>>>(bv, lv, biasVG, cscVG);

    const dim3 grid_vg(NAUG / BN, MTOT / BM, 1);     // (13, 256, 1)
    const dim3 grid_qk(S_ / BN, S_ / BM, B_);        // (8, 8, 32)
    const dim3 grid_pv(D_ / BN, S_ / BM, B_);        // (6, 8, 32)

    for (int l = 0; l < L_; l++) {
        // GV = h @ [M | w1 | w2 | pad | Wv]  (+biasVG)(*cscVG)  (NN)
        gemm_mma<1,1><<<grid_vg, blk, GEMM_SMEM_NN>>>(
            hh, hl, Baugh + (long)l * LB, Baugl + (long)l * LB, nullptr, GVh, GVl,
            biasVG + (long)l * NAUG, cscVG + (long)l * NAUG, 1.0f,
            D_, D_, NAUG, NAUG, 0, 0, 0);

        // u, w vectors
        extract_uw<<<MTOT / 256, blk>>>(GVh, GVl, cArr, l, U, W);

        // P = G @ h^T  (alpha already folded into M)  (NT, batched)
        gemm_mma<0,0><<<grid_qk, blk, GEMM_SMEM_NT>>>(
            GVh, GVl, hh, hl, P, nullptr, nullptr,
            nullptr, nullptr, 1.0f, D_, NAUG, D_, S_, SGVl, SD, SS);

        // softmax(P + u + w) -> split bf16
        softmax_split<<<B_ * S_, blk>>>(P, U, W, Ph, Pl);

        // h = P @ V  (V = GV cols 896.., NN trans-ldmatrix, batched)
        gemm_mma<1,1><<<grid_pv, blk, GEMM_SMEM_NN>>>(
            Ph, Pl, GVh + VOFF, GVl + VOFF, nullptr, hh, hl,
            nullptr, nullptr, 1.0f, S_, S_, NAUG, D_, SS, SGVl, SD);
    }

    head_kernel<<<B_, blk>>>(hh, hl, Whead, bhead, out);
}

// round 14
// speedup vs baseline: 2.8112x; 1.0000x over previous
#include <cuda_runtime.h>
#include <cuda_bf16.h>
#include <math.h>
#include <stdint.h>

#define B_ 32
#define S_ 1024
#define D_ 768
#define L_ 12
#define MTOT (B_*S_)
#define NAUG 1536                    // [M(768) | Wv(768)]
#define VOFF 768
#define LB ((long)D_*NAUG)           // per-layer Baug stride

// ===================== scratch (__device__ globals; no allocs) =====================
__device__ __align__(16) __nv_bfloat16 g_hh  [(size_t)MTOT*D_];
__device__ __align__(16) __nv_bfloat16 g_hl  [(size_t)MTOT*D_];
__device__ __align__(16) __nv_bfloat16 g_GVh [(size_t)MTOT*NAUG];   // [G | V]
__device__ __align__(16) __nv_bfloat16 g_GVl [(size_t)MTOT*NAUG];
__device__ __align__(16) float         g_P   [(size_t)B_*S_*S_];
__device__ __align__(16) __nv_bfloat16 g_Ph  [(size_t)B_*S_*S_];
__device__ __align__(16) __nv_bfloat16 g_Pl  [(size_t)B_*S_*S_];
__device__ __align__(16) __nv_bfloat16 g_Baugh[(size_t)L_*D_*NAUG];
__device__ __align__(16) __nv_bfloat16 g_Baugl[(size_t)L_*D_*NAUG];
__device__ __align__(16) __nv_bfloat16 g_Wqsh[(size_t)L_*D_*D_];    // Wq split (straight)
__device__ __align__(16) __nv_bfloat16 g_Wqsl[(size_t)L_*D_*D_];
__device__ __align__(16) __nv_bfloat16 g_Wksh[(size_t)L_*D_*D_];    // Wk*lk split
__device__ __align__(16) __nv_bfloat16 g_Wksl[(size_t)L_*D_*D_];
__device__ float g_biasVG[(size_t)L_*NAUG];
__device__ float g_cscVG [(size_t)L_*NAUG];
__device__ float g_w1[(size_t)L_*D_];    // alpha * Wq (lk .* bk)
__device__ float g_w2[(size_t)L_*D_];    // alpha * Wk (lk .* bq)
__device__ float g_U[MTOT];
__device__ float g_W[MTOT];
__device__ float g_c[L_];

// ===================== PTX helpers (generic sm_80+ features only) =====================
__device__ __forceinline__ uint32_t smem_u32(const void* p) {
    uint32_t a;
    asm("{ .reg .u64 t; cvta.to.shared.u64 t, %1; cvt.u32.u64 %0, t; }" : "=r"(a) : "l"(p));
    return a;
}
__device__ __forceinline__ void cpa16(uint32_t s, const void* g) {
    asm volatile("cp.async.cg.shared.global [%0], [%1], 16;" :: "r"(s), "l"(g));
}
#define CP_COMMIT() asm volatile("cp.async.commit_group;" ::: "memory")
#define CP_WAIT1()  asm volatile("cp.async.wait_group 1;" ::: "memory")

__device__ __forceinline__ void ldm_x4(uint32_t& r0, uint32_t& r1, uint32_t& r2, uint32_t& r3,
                                       uint32_t a) {
    asm volatile("ldmatrix.sync.aligned.m8n8.x4.shared.b16 {%0,%1,%2,%3}, [%4];"
                 : "=r"(r0), "=r"(r1), "=r"(r2), "=r"(r3) : "r"(a));
}
__device__ __forceinline__ void ldm_x4t(uint32_t& r0, uint32_t& r1, uint32_t& r2, uint32_t& r3,
                                        uint32_t a) {
    asm volatile("ldmatrix.sync.aligned.m8n8.x4.trans.shared.b16 {%0,%1,%2,%3}, [%4];"
                 : "=r"(r0), "=r"(r1), "=r"(r2), "=r"(r3) : "r"(a));
}
__device__ __forceinline__ void mma_bf16(float* c, const uint32_t* a, const uint32_t* b) {
    asm volatile("mma.sync.aligned.m16n8k16.row.col.f32.bf16.bf16.f32 "
                 "{%0,%1,%2,%3}, {%4,%5,%6,%7}, {%8,%9}, {%0,%1,%2,%3};"
                 : "+f"(c[0]), "+f"(c[1]), "+f"(c[2]), "+f"(c[3])
                 : "r"(a[0]), "r"(a[1]), "r"(a[2]), "r"(a[3]), "r"(b[0]), "r"(b[1]));
}

// ===================== GEMM ==============
// BTRANS=0: Bt [N,K] row-major (NT).   BTRANS=1: B [K,N] row-major (NN, trans-ldmatrix).
// A: [M,K] row-major split (Ah,Al).  bf16x3: acc += AhBh + AhBl + AlBh (fp32 accum).
// OUT=0: fp32 C.  OUT=1: bf16 hi/lo split (Ch, Cl).
#define BM 128
#define BN 128
#define BKE 32
#define ROWB 80
#define TILEB (128 * ROWB)            // 10240 B
#define BT_ROWB 272                   // 256B + 16B pad; 17 units mod 8 = 1
#define BT_TILE (32 * BT_ROWB)        // 8704 B

template<int OUT, int BTRANS>
__global__ __launch_bounds__(256, 2)
void gemm_mma(const __nv_bfloat16* __restrict__ Ah, const __nv_bfloat16* __restrict__ Al,
              const __nv_bfloat16* __restrict__ Bh, const __nv_bfloat16* __restrict__ Bl,
              float* __restrict__ Cf,
              __nv_bfloat16* __restrict__ Ch, __nv_bfloat16* __restrict__ Cl,
              const float* __restrict__ bias, const float* __restrict__ csc,
              float alpha, int K, int lda, int ldb, int ldc,
              long sA, long sB, long sC)
{
    constexpr int BTILEB = BTRANS ? BT_TILE : TILEB;
    constexpr int STAGEB = 2 * TILEB + 2 * BTILEB;

    extern __shared__ char smem[];
    const uint32_t sbase = smem_u32(smem);
    const int tid = threadIdx.x;
    const int lane = tid & 31, wid = tid >> 5;
    const int wm = wid & 3, wn = wid >> 2;
    const int z = blockIdx.z;
    Ah += z * sA;  Al += z * sA;
    Bh += z * sB;  Bl += z * sB;

    const long tileM = blockIdx.y * (long)BM;
    const long tileN = blockIdx.x * (long)BN;

    const __nv_bfloat16* gAh = Ah + tileM * lda;
    const __nv_bfloat16* gAl = Al + tileM * lda;
    const __nv_bfloat16* gBh = BTRANS ? Bh : (Bh + tileN * ldb);
    const __nv_bfloat16* gBl = BTRANS ? Bl : (Bl + tileN * ldb);

    const int r0q = tid >> 2, c0q = tid & 3;

    auto load_stage = [&](int stage, int k0) {
        const uint32_t sb = sbase + stage * STAGEB;
        #pragma unroll
        for (int it = 0; it < 2; it++) {
            const int r = r0q + it * 64;
            const long go = (long)r * lda + k0 + c0q * 8;
            const uint32_t so = r * ROWB + c0q * 16;
            cpa16(sb + 0 * TILEB + so, gAh + go);
            cpa16(sb + 1 * TILEB + so, gAl + go);
        }
        if (BTRANS) {
            #pragma unroll
            for (int it = 0; it < 2; it++) {
                const int idx = tid + it * 256;
                const int r = idx >> 4, c = idx & 15;
                const long go = (long)(k0 + r) * ldb + tileN + c * 8;
                const uint32_t so = r * BT_ROWB + c * 16;
                cpa16(sb + 2 * TILEB + so, gBh + go);
                cpa16(sb + 2 * TILEB + BTILEB + so, gBl + go);
            }
        } else {
            #pragma unroll
            for (int it = 0; it < 2; it++) {
                const int r = r0q + it * 64;
                const long gb = (long)r * ldb + k0 + c0q * 8;
                const uint32_t so = r * ROWB + c0q * 16;
                cpa16(sb + 2 * TILEB + so, gBh + gb);
                cpa16(sb + 2 * TILEB + BTILEB + so, gBl + gb);
            }
        }
        CP_COMMIT();
    };

    float acc[2][8][4];
    #pragma unroll
    for (int i = 0; i < 2; i++)
        #pragma unroll
        for (int j = 0; j < 8; j++)
            #pragma unroll
            for (int q = 0; q < 4; q++) acc[i][j][q] = 0.f;

    const int nk = K / BKE;
    load_stage(0, 0);
    load_stage(1, BKE);

    const int a_row  = wm * 32 + (lane & 15);
    const int b_row  = wn * 64 + (lane & 7) + ((lane >> 3) & 1) * 8;
    const int colb   = (lane >> 4) * 16;
    const int bt_k   = ((lane >> 4) & 1) * 8 + (lane & 7);
    const int bt_n   = wn * 64 + ((lane >> 3) & 1) * 8;

    for (int i = 0; i < nk; i++) {
        CP_WAIT1();
        __syncthreads();
        const uint32_t sb = sbase + (i & 1) * STAGEB;

        #pragma unroll
        for (int ks = 0; ks < 2; ks++) {
            uint32_t ah[2][4], al[2][4], bh[8][2], bl[8][2];
            #pragma unroll
            for (int ma = 0; ma < 2; ma++) {
                const uint32_t ad = sb + (a_row + ma * 16) * ROWB + ks * 32 + colb;
                ldm_x4(ah[ma][0], ah[ma][1], ah[ma][2], ah[ma][3], ad);
                ldm_x4(al[ma][0], al[ma][1], al[ma][2], al[ma][3], ad + TILEB);
            }
            #pragma unroll
            for (int nb = 0; nb < 4; nb++) {
                uint32_t t0, t1, t2, t3;
                if (BTRANS) {
                    const uint32_t bd = sb + 2 * TILEB
                                      + (ks * 16 + bt_k) * BT_ROWB
                                      + (bt_n + nb * 16) * 2;
                    ldm_x4t(t0, t1, t2, t3, bd);
                    bh[2*nb][0] = t0; bh[2*nb][1] = t2; bh[2*nb+1][0] = t1; bh[2*nb+1][1] = t3;
                    ldm_x4t(t0, t1, t2, t3, bd + BTILEB);
                    bl[2*nb][0] = t0; bl[2*nb][1] = t2; bl[2*nb+1][0] = t1; bl[2*nb+1][1] = t3;
                } else {
                    const uint32_t bd = sb + 2 * TILEB + (b_row + nb * 16) * ROWB + ks * 32 + colb;
                    ldm_x4(t0, t1, t2, t3, bd);
                    bh[2*nb][0] = t0; bh[2*nb][1] = t2; bh[2*nb+1][0] = t1; bh[2*nb+1][1] = t3;
                    ldm_x4(t0, t1, t2, t3, bd + BTILEB);
                    bl[2*nb][0] = t0; bl[2*nb][1] = t2; bl[2*nb+1][0] = t1; bl[2*nb+1][1] = t3;
                }
            }
            #pragma unroll
            for (int ma = 0; ma < 2; ma++)
                #pragma unroll
                for (int na = 0; na < 8; na++) mma_bf16(acc[ma][na], ah[ma], bh[na]);
            #pragma unroll
            for (int ma = 0; ma < 2; ma++)
                #pragma unroll
                for (int na = 0; na < 8; na++) mma_bf16(acc[ma][na], ah[ma], bl[na]);
            #pragma unroll
            for (int ma = 0; ma < 2; ma++)
                #pragma unroll
                for (int na = 0; na < 8; na++) mma_bf16(acc[ma][na], al[ma], bh[na]);
        }

        __syncthreads();
        if (i + 2 < nk) load_stage(i & 1, (i + 2) * BKE);
        else CP_COMMIT();
    }

    // ===================== epilogue =====================
    const int gq = lane >> 2, rq = lane & 3;
    #pragma unroll
    for (int ma = 0; ma < 2; ma++) {
        #pragma unroll
        for (int half = 0; half < 2; half++) {
            const long row = tileM + wm * 32 + ma * 16 + gq + half * 8;
            #pragma unroll
            for (int na = 0; na < 8; na++) {
                const long col = tileN + wn * 64 + na * 8 + rq * 2;
                float v0 = acc[ma][na][half * 2 + 0] * alpha;
                float v1 = acc[ma][na][half * 2 + 1] * alpha;
                if (bias) { v0 += bias[col]; v1 += bias[col + 1]; }
                if (csc)  { v0 *= csc[col];  v1 *= csc[col + 1]; }
                if (OUT == 0) {
                    float2 f2; f2.x = v0; f2.y = v1;
                    *(float2*)(Cf + z * sC + row * ldc + col) = f2;
                } else {
                    const __nv_bfloat16 h0 = __float2bfloat16(v0);
                    const __nv_bfloat16 h1 = __float2bfloat16(v1);
                    const __nv_bfloat16 l0 = __float2bfloat16(v0 - __bfloat162float(h0));
                    const __nv_bfloat16 l1 = __float2bfloat16(v1 - __bfloat162float(h1));
                    __nv_bfloat162 hp; hp.x = h0; hp.y = h1;
                    __nv_bfloat162 lp; lp.x = l0; lp.y = l1;
                    *(__nv_bfloat162*)(Ch + z * sC + row * ldc + col) = hp;
                    *(__nv_bfloat162*)(Cl + z * sC + row * ldc + col) = lp;
                }
            }
        }
    }
}

#define GEMM_SMEM_NT (2 * (2 * TILEB + 2 * TILEB))     // 81920
#define GEMM_SMEM_NN (2 * (2 * TILEB + 2 * BT_TILE))   // 75776

// ===================== elementwise fp32 -> bf16 hi/lo split (contiguous) ============
__global__ __launch_bounds__(256)
void split_kernel(const float* __restrict__ X, __nv_bfloat16* __restrict__ Xh,
                  __nv_bfloat16* __restrict__ Xl)
{
    const long i = ((long)blockIdx.x * 256 + threadIdx.x) * 4;
    const float4 f = *(const float4*)(X + i);
    float v[4] = {f.x, f.y, f.z, f.w};
    __nv_bfloat16 h[4], l[4];
    #pragma unroll
    for (int k = 0; k < 4; k++) {
        h[k] = __float2bfloat16(v[k]);
        l[k] = __float2bfloat16(v[k] - __bfloat162float(h[k]));
    }
    *(uint2*)(Xh + i) = *(const uint2*)h;
    *(uint2*)(Xl + i) = *(const uint2*)l;
}

// ===================== split with optional column scale, strided dst =================
__global__ __launch_bounds__(256)
void split_cs(const float* __restrict__ X, const float* __restrict__ sc,
              __nv_bfloat16* __restrict__ Dh, __nv_bfloat16* __restrict__ Dl,
              int C, int ldD, int off, long sX, long sSc, long sD)
{
    const int z = blockIdx.z;
    X += z * sX;
    if (sc) sc += z * sSc;
    Dh += z * sD;
    Dl += z * sD;
    const long idx = ((long)blockIdx.x * 256 + threadIdx.x) * 4;
    const int r = (int)(idx / C), c = (int)(idx % C);
    const float4 f = *(const float4*)(X + idx);
    float v[4] = {f.x, f.y, f.z, f.w};
    __nv_bfloat16 h[4], l[4];
    #pragma unroll
    for (int k = 0; k < 4; k++) {
        const float s = sc ? sc[c + k] : 1.0f;
        const float x = v[k] * s;
        h[k] = __float2bfloat16(x);
        l[k] = __float2bfloat16(x - __bfloat162float(h[k]));
    }
    const long o = (long)r * ldD + off + c;
    *(uint2*)(Dh + o) = *(const uint2*)h;
    *(uint2*)(Dl + o) = *(const uint2*)l;
}

// ===================== pack VG bias / csc =====================
__global__ __launch_bounds__(256)
void pack_vg(const float* __restrict__ bv, const float* __restrict__ lv,
             float* __restrict__ biasVG, float* __restrict__ cscVG)
{
    const int idx = blockIdx.x * 256 + threadIdx.x;    // over L_*NAUG = 18432 (exact)
    const int l = idx / NAUG, c = idx % NAUG;
    biasVG[idx] = (c >= VOFF) ? bv[l * D_ + (c - VOFF)] : 0.0f;
    cscVG[idx]  = (c >= VOFF) ? lv[l * D_ + (c - VOFF)] : 1.0f;
}

// ===================== bias-correction vectors (fp32) =====================
// w1[l,d] = alpha * sum_e Wq[l,d,e] lk[l,e] bk[l,e];  w2 likewise with Wk, bq.
__global__ __launch_bounds__(256)
void wvec(const float* __restrict__ Wq, const float* __restrict__ Wk,
          const float* __restrict__ bq, const float* __restrict__ bk,
          const float* __restrict__ lk,
          float* __restrict__ w1, float* __restrict__ w2, float alpha)
{
    const int l = blockIdx.z;
    const int d = blockIdx.x * 256 + threadIdx.x;      // grid.x = 3
    const float* wq = Wq + (long)l * D_ * D_ + (long)d * D_;
    const float* wk = Wk + (long)l * D_ * D_ + (long)d * D_;
    const float* bqz = bq + (long)l * D_;
    const float* bkz = bk + (long)l * D_;
    const float* lkz = lk + (long)l * D_;
    float a1 = 0.f, a2 = 0.f;
    for (int e = 0; e < D_; e++) {
        const float le = lkz[e];
        a1 += wq[e] * le * bkz[e];
        a2 += wk[e] * le * bqz[e];
    }
    w1[(long)l * D_ + d] = alpha * a1;
    w2[(long)l * D_ + d] = alpha * a2;
}

// ===================== c constant per layer =====================
__global__ __launch_bounds__(256)
void c_kernel(const float* __restrict__ bq, const float* __restrict__ bk,
              const float* __restrict__ lk, float* __restrict__ cOut, float alpha)
{
    const int l = blockIdx.x;
    const int tid = threadIdx.x;
    __shared__ float red[8];
    float s = 0.f;
    for (int e = tid; e < D_; e += 256)
        s += bq[l * D_ + e] * lk[l * D_ + e] * bk[l * D_ + e];
    #pragma unroll
    for (int o = 16; o; o >>= 1) s += __shfl_xor_sync(0xFFFFFFFFu, s, o);
    if ((tid & 31) == 0) red[tid >> 5] = s;
    __syncthreads();
    if (tid == 0) {
        float t = 0.f;
        #pragma unroll
        for (int w = 0; w < 8; w++) t += red[w];
        cOut[l] = alpha * t;
    }
}

// ===================== u,w per row: dot(h, w1)+c, dot(h, w2) =====================
__global__ __launch_bounds__(256)
void uw_kernel(const __nv_bfloat16* __restrict__ hh, const __nv_bfloat16* __restrict__ hl,
               const float* __restrict__ w1, const float* __restrict__ w2,
               const float* __restrict__ cAll, int l,
               float* __restrict__ U, float* __restrict__ W)
{
    const long row = blockIdx.x;
    const long base = row * D_;
    const int tid = threadIdx.x;
    __shared__ float red1[8], red2[8];

    float s1 = 0.f, s2 = 0.f;
    #pragma unroll
    for (int q = 0; q < 3; q++) {
        const int d = tid + q * 256;
        const float x = __bfloat162float(hh[base + d]) + __bfloat162float(hl[base + d]);
        s1 += x * w1[d];
        s2 += x * w2[d];
    }
    #pragma unroll
    for (int o = 16; o; o >>= 1) {
        s1 += __shfl_xor_sync(0xFFFFFFFFu, s1, o);
        s2 += __shfl_xor_sync(0xFFFFFFFFu, s2, o);
    }
    if ((tid & 31) == 0) { red1[tid >> 5] = s1; red2[tid >> 5] = s2; }
    __syncthreads();
    if (tid == 0) {
        float t1 = 0.f, t2 = 0.f;
        #pragma unroll
        for (int w = 0; w < 8; w++) { t1 += red1[w]; t2 += red2[w]; }
        U[row] = t1 + cAll[l];
        W[row] = t2;
    }
}

// ===================== row softmax (+u,+w): fp32 in -> bf16 hi/lo out ================
__global__ __launch_bounds__(256)
void softmax_split(const float* __restrict__ P, const float* __restrict__ U,
                   const float* __restrict__ W,
                   __nv_bfloat16* __restrict__ Ph, __nv_bfloat16* __restrict__ Pl)
{
    const long row = blockIdx.x;
    const int tid = threadIdx.x;
    __shared__ float red[8];

    const float4 f = *(const float4*)(P + row * S_ + tid * 4);
    const long wbase = (row >> 10) << 10;              // b * S
    const float4 wv = *(const float4*)(W + wbase + tid * 4);
    const float uv = U[row];
    float v[4] = {f.x + uv + wv.x, f.y + uv + wv.y, f.z + uv + wv.z, f.w + uv + wv.w};

    float m = fmaxf(fmaxf(v[0], v[1]), fmaxf(v[2], v[3]));
    #pragma unroll
    for (int o = 16; o; o >>= 1) m = fmaxf(m, __shfl_xor_sync(0xFFFFFFFFu, m, o));
    if ((tid & 31) == 0) red[tid >> 5] = m;
    __syncthreads();
    if (tid < 8) {
        float t = red[tid];
        #pragma unroll
        for (int o = 4; o; o >>= 1) t = fmaxf(t, __shfl_xor_sync(0xFFu, t, o));
        if (tid == 0) red[0] = t;
    }
    __syncthreads();
    m = red[0];
    __syncthreads();

    float s = 0.f;
    #pragma unroll
    for (int k = 0; k < 4; k++) { v[k] = __expf(v[k] - m); s += v[k]; }
    #pragma unroll
    for (int o = 16; o; o >>= 1) s += __shfl_xor_sync(0xFFFFFFFFu, s, o);
    if ((tid & 31) == 0) red[tid >> 5] = s;
    __syncthreads();
    if (tid < 8) {
        float t = red[tid];
        #pragma unroll
        for (int o = 4; o; o >>= 1) t += __shfl_xor_sync(0xFFu, t, o);
        if (tid == 0) red[0] = t;
    }
    __syncthreads();
    const float inv = 1.f / red[0];

    __nv_bfloat16 h[4], l[4];
    #pragma unroll
    for (int k = 0; k < 4; k++) {
        const float p = v[k] * inv;
        h[k] = __float2bfloat16(p);
        l[k] = __float2bfloat16(p - __bfloat162float(h[k]));
    }
    *(uint2*)(Ph + row * S_ + tid * 4) = *(const uint2*)h;
    *(uint2*)(Pl + row * S_ + tid * 4) = *(const uint2*)l;
}

// ===================== head =====================
__global__ __launch_bounds__(256)
void head_kernel(const __nv_bfloat16* __restrict__ hh, const __nv_bfloat16* __restrict__ hl,
                 const float* __restrict__ Wh, const float* __restrict__ bh,
                 float* __restrict__ out)
{
    const int b = blockIdx.x;
    const long base = (long)b * S_ * D_;
    const int tid = threadIdx.x;
    __shared__ float red[8];

    float s = 0.f;
    for (int d = tid; d < D_; d += 256)
        s += (__bfloat162float(hh[base + d]) + __bfloat162float(hl[base + d])) * Wh[d];
    #pragma unroll
    for (int o = 16; o; o >>= 1) s += __shfl_xor_sync(0xFFFFFFFFu, s, o);
    if ((tid & 31) == 0) red[tid >> 5] = s;
    __syncthreads();
    if (tid == 0) {
        float t = 0.f;
        #pragma unroll
        for (int w = 0; w < 8; w++) t += red[w];
        out[b] = t + bh[0];
    }
}

// ===================== driver =====================
extern "C" void kernel_launch(void* const* d_in, const int* in_sizes, int n_in,
                              void* d_out, int out_size)
{
    const float* hs    = (const float*)d_in[0];
    const float* Wq    = (const float*)d_in[1];
    const float* bq    = (const float*)d_in[2];
    const float* Wk    = (const float*)d_in[3];
    const float* bk    = (const float*)d_in[4];
    const float* Wv    = (const float*)d_in[5];
    const float* bv    = (const float*)d_in[6];
    const float* lk    = (const float*)d_in[7];
    const float* lv    = (const float*)d_in[8];
    const float* Whead = (const float*)d_in[9];
    const float* bhead = (const float*)d_in[10];
    float* out = (float*)d_out;

    __nv_bfloat16 *hh, *hl, *GVh, *GVl, *Ph, *Pl, *Baugh, *Baugl;
    __nv_bfloat16 *Wqsh, *Wqsl, *Wksh, *Wksl;
    float *P, *biasVG, *cscVG, *w1, *w2, *U, *W, *cArr;
    cudaGetSymbolAddress((void**)&hh,   g_hh);    cudaGetSymbolAddress((void**)&hl,   g_hl);
    cudaGetSymbolAddress((void**)&GVh,  g_GVh);   cudaGetSymbolAddress((void**)&GVl,  g_GVl);
    cudaGetSymbolAddress((void**)&P,    g_P);
    cudaGetSymbolAddress((void**)&Ph,   g_Ph);    cudaGetSymbolAddress((void**)&Pl,   g_Pl);
    cudaGetSymbolAddress((void**)&Baugh, g_Baugh); cudaGetSymbolAddress((void**)&Baugl, g_Baugl);
    cudaGetSymbolAddress((void**)&Wqsh, g_Wqsh);  cudaGetSymbolAddress((void**)&Wqsl, g_Wqsl);
    cudaGetSymbolAddress((void**)&Wksh, g_Wksh);  cudaGetSymbolAddress((void**)&Wksl, g_Wksl);
    cudaGetSymbolAddress((void**)&biasVG, g_biasVG);
    cudaGetSymbolAddress((void**)&cscVG,  g_cscVG);
    cudaGetSymbolAddress((void**)&w1,   g_w1);    cudaGetSymbolAddress((void**)&w2,   g_w2);
    cudaGetSymbolAddress((void**)&U,    g_U);     cudaGetSymbolAddress((void**)&W,    g_W);
    cudaGetSymbolAddress((void**)&cArr, g_c);

    cudaFuncSetAttribute((const void*)gemm_mma<0,0>, cudaFuncAttributeMaxDynamicSharedMemorySize, GEMM_SMEM_NT);
    cudaFuncSetAttribute((const void*)gemm_mma<1,0>, cudaFuncAttributeMaxDynamicSharedMemorySize, GEMM_SMEM_NT);
    cudaFuncSetAttribute((const void*)gemm_mma<1,1>, cudaFuncAttributeMaxDynamicSharedMemorySize, GEMM_SMEM_NN);

    const float attn_alpha = 1.0f / sqrtf((float)D_);
    const long SD  = (long)S_ * D_;
    const long SS  = (long)S_ * S_;
    const long DD  = (long)D_ * D_;
    const long SGVl = (long)S_ * NAUG;

    const dim3 blk(256);

    // ================= one-time prep =================
    split_kernel<<<(MTOT * D_) / (256 * 4), blk>>>(hs, hh, hl);
    split_cs<<<dim3(DD / 1024, 1, L_), blk>>>(Wq, nullptr, Wqsh, Wqsl, D_, D_, 0, DD, 0, DD);
    split_cs<<<dim3(DD / 1024, 1, L_), blk>>>(Wk, lk,      Wksh, Wksl, D_, D_, 0, DD, (long)D_, DD);
    split_cs<<<dim3(DD / 1024, 1, L_), blk>>>(Wv, nullptr, Baugh, Baugl, D_, NAUG, VOFF, DD, 0, LB);
    // M = alpha * Wq @ (Wk*lk)^T  -> Baug cols 0..767  (NT, batched over layers)
    gemm_mma<1,0><<<dim3(D_/BN, D_/BM, L_), blk, GEMM_SMEM_NT>>>(
        Wqsh, Wqsl, Wksh, Wksl, nullptr, Baugh, Baugl,
        nullptr, nullptr, attn_alpha, D_, D_, D_, NAUG, DD, DD, LB);
    wvec<<<dim3(3, 1, L_), blk>>>(Wq, Wk, bq, bk, lk, w1, w2, attn_alpha);
    c_kernel<<<L_, blk>>>(bq, bk, lk, cArr, attn_alpha);
    pack_vg<<<(L_ * NAUG) / 256, blk>>>(bv, lv, biasVG, cscVG);

    const dim3 grid_vg(NAUG / BN, MTOT / BM, 1);     // (12, 256, 1)
    const dim3 grid_qk(S_ / BN, S_ / BM, B_);        // (8, 8, 32)
    const dim3 grid_pv(D_ / BN, S_ / BM, B_);        // (6, 8, 32)

    for (int l = 0; l < L_; l++) {
        // GV = h @ [M | Wv]  (+biasVG)(*cscVG)  (NN)
        gemm_mma<1,1><<<grid_vg, blk, GEMM_SMEM_NN>>>(
            hh, hl, Baugh + (long)l * LB, Baugl + (long)l * LB, nullptr, GVh, GVl,
            biasVG + (long)l * NAUG, cscVG + (long)l * NAUG, 1.0f,
            D_, D_, NAUG, NAUG, 0, 0, 0);

        // u, w vectors from h (fp32 dots, off tensor pipe)
        uw_kernel<<<MTOT, blk>>>(hh, hl, w1 + (long)l * D_, w2 + (long)l * D_, cArr, l, U, W);

        // P = G @ h^T  (alpha already folded into M)  (NT, batched)
        gemm_mma<0,0><<<grid_qk, blk, GEMM_SMEM_NT>>>(
            GVh, GVl, hh, hl, P, nullptr, nullptr,
            nullptr, nullptr, 1.0f, D_, NAUG, D_, S_, SGVl, SD, SS);

        // softmax(P + u + w) -> split bf16
        softmax_split<<<B_ * S_, blk>>>(P, U, W, Ph, Pl);

        // h = P @ V  (V = GV cols 768.., NN trans-ldmatrix, batched)
        gemm_mma<1,1><<<grid_pv, blk, GEMM_SMEM_NN>>>(
            Ph, Pl, GVh + VOFF, GVl + VOFF, nullptr, hh, hl,
            nullptr, nullptr, 1.0f, S_, S_, NAUG, D_, SS, SGVl, SD);
    }

    head_kernel<<<B_, blk>>>(hh, hl, Whead, bhead, out);
}